// round 2
// baseline (speedup 1.0000x reference)
#include <cuda_runtime.h>
#include <math.h>

#define B_ 2
#define L_ 64
#define C_ 256
#define S_ 256
#define D_ 512
#define NQ (B_*L_*C_)   /* 32768 rows for q / k / v / att */

// Scratch (module-load allocated; no runtime allocs)
__device__ float g_q  [(size_t)NQ * D_];
__device__ float g_k  [(size_t)NQ * D_];
__device__ float g_v  [(size_t)NQ * D_];
__device__ float g_att[(size_t)NQ * D_];

// ---------------------------------------------------------------------------
// NT GEMM with bias: C[M,N] = A[M,K] * B[N,K]^T + bias[N]
// 128x128 block tile, BK=8, 256 threads, 8x8 per-thread microtile.
// M,N multiples of 128; K multiple of 8.
// ---------------------------------------------------------------------------
__global__ __launch_bounds__(256) void gemm_nt_bias(
    const float* __restrict__ A, const float* __restrict__ Bm,
    const float* __restrict__ bias, float* __restrict__ C,
    int M, int N, int K)
{
    __shared__ float As[8][128];
    __shared__ float Bs[8][128];

    const int tid = threadIdx.x;
    const int tx  = tid & 15;
    const int ty  = tid >> 4;
    const int row0 = blockIdx.y * 128;
    const int col0 = blockIdx.x * 128;

    const int lrow = tid >> 1;          // 0..127
    const int lk   = (tid & 1) * 4;     // 0 or 4
    const float* Ap = A  + (size_t)(row0 + lrow) * K + lk;
    const float* Bp = Bm + (size_t)(col0 + lrow) * K + lk;

    float acc[8][8];
#pragma unroll
    for (int i = 0; i < 8; i++)
#pragma unroll
        for (int j = 0; j < 8; j++) acc[i][j] = 0.0f;

    for (int k0 = 0; k0 < K; k0 += 8) {
        float4 a = *(const float4*)(Ap + k0);
        float4 b = *(const float4*)(Bp + k0);
        As[lk+0][lrow] = a.x; As[lk+1][lrow] = a.y;
        As[lk+2][lrow] = a.z; As[lk+3][lrow] = a.w;
        Bs[lk+0][lrow] = b.x; Bs[lk+1][lrow] = b.y;
        Bs[lk+2][lrow] = b.z; Bs[lk+3][lrow] = b.w;
        __syncthreads();

#pragma unroll
        for (int kk = 0; kk < 8; kk++) {
            float ra[8], rb[8];
            *(float4*)&ra[0] = *(const float4*)&As[kk][ty * 8 + 0];
            *(float4*)&ra[4] = *(const float4*)&As[kk][ty * 8 + 4];
            *(float4*)&rb[0] = *(const float4*)&Bs[kk][tx * 8 + 0];
            *(float4*)&rb[4] = *(const float4*)&Bs[kk][tx * 8 + 4];
#pragma unroll
            for (int i = 0; i < 8; i++)
#pragma unroll
                for (int j = 0; j < 8; j++)
                    acc[i][j] = fmaf(ra[i], rb[j], acc[i][j]);
        }
        __syncthreads();
    }

    float bv[8];
#pragma unroll
    for (int j = 0; j < 8; j++) bv[j] = bias[col0 + tx * 8 + j];

#pragma unroll
    for (int i = 0; i < 8; i++) {
        float* cp = C + (size_t)(row0 + ty * 8 + i) * N + col0 + tx * 8;
        float4 o0, o1;
        o0.x = acc[i][0] + bv[0]; o0.y = acc[i][1] + bv[1];
        o0.z = acc[i][2] + bv[2]; o0.w = acc[i][3] + bv[3];
        o1.x = acc[i][4] + bv[4]; o1.y = acc[i][5] + bv[5];
        o1.z = acc[i][6] + bv[6]; o1.w = acc[i][7] + bv[7];
        *(float4*)(cp + 0) = o0;
        *(float4*)(cp + 4) = o1;
    }
}

// ---------------------------------------------------------------------------
// Attention: per block handles one (b,l) pair and a 64-row query tile.
//   S = scale * Q Kt   [64,256]   (K-dim 512)
//   P = softmax_rows(S)
//   O = P V            [64,512]   (computed in two 256-wide d halves)
// 256 threads = 16(ty) x 16(tx); thread owns 4x16 of the 64x256 tile.
// ---------------------------------------------------------------------------
__global__ __launch_bounds__(256) void attn_kernel(
    const float* __restrict__ q, const float* __restrict__ k,
    const float* __restrict__ v, float* __restrict__ o)
{
    extern __shared__ float sm[];
    const int tid = threadIdx.x;
    const int tx  = tid & 15;
    const int ty  = tid >> 4;
    const int bl  = blockIdx.x >> 2;   // 0..127 (b*l)
    const int ct  = blockIdx.x & 3;    // 0..3 query tile

    const float* Qb = q + (size_t)bl * C_ * D_ + (size_t)ct * 64 * D_;
    const float* Kb = k + (size_t)bl * S_ * D_;
    const float* Vb = v + (size_t)bl * S_ * D_;

    float acc[4][16];
#pragma unroll
    for (int i = 0; i < 4; i++)
#pragma unroll
        for (int j = 0; j < 16; j++) acc[i][j] = 0.0f;

    // ---- Phase 1: S = Q * K^T ----
    float* Qs = sm;             // [16][64]  k-major
    float* Ks = sm + 16 * 64;   // [16][256] k-major
    const int qr = tid >> 2;          // 0..63
    const int qk = (tid & 3) * 4;     // 0,4,8,12

    for (int k0 = 0; k0 < D_; k0 += 16) {
        float4 a = *(const float4*)(Qb + (size_t)qr * D_ + k0 + qk);
        Qs[(qk+0)*64 + qr] = a.x; Qs[(qk+1)*64 + qr] = a.y;
        Qs[(qk+2)*64 + qr] = a.z; Qs[(qk+3)*64 + qr] = a.w;
#pragma unroll
        for (int i = 0; i < 4; i++) {
            int r = qr + i * 64;
            float4 b = *(const float4*)(Kb + (size_t)r * D_ + k0 + qk);
            Ks[(qk+0)*256 + r] = b.x; Ks[(qk+1)*256 + r] = b.y;
            Ks[(qk+2)*256 + r] = b.z; Ks[(qk+3)*256 + r] = b.w;
        }
        __syncthreads();

#pragma unroll
        for (int kk = 0; kk < 16; kk++) {
            float rq[4], rk[16];
            rq[0] = Qs[kk*64 + ty*4 + 0];
            rq[1] = Qs[kk*64 + ty*4 + 1];
            rq[2] = Qs[kk*64 + ty*4 + 2];
            rq[3] = Qs[kk*64 + ty*4 + 3];
            *(float4*)&rk[0]  = *(const float4*)&Ks[kk*256 + tx*16 + 0];
            *(float4*)&rk[4]  = *(const float4*)&Ks[kk*256 + tx*16 + 4];
            *(float4*)&rk[8]  = *(const float4*)&Ks[kk*256 + tx*16 + 8];
            *(float4*)&rk[12] = *(const float4*)&Ks[kk*256 + tx*16 + 12];
#pragma unroll
            for (int i = 0; i < 4; i++)
#pragma unroll
                for (int j = 0; j < 16; j++)
                    acc[i][j] = fmaf(rq[i], rk[j], acc[i][j]);
        }
        __syncthreads();
    }

    // ---- Phase 2: softmax over rows (each row split across 16 tx lanes) ----
    const float scale = 0.04419417382415922f;   // 1/sqrt(512)
#pragma unroll
    for (int i = 0; i < 4; i++) {
        float m = -1e30f;
#pragma unroll
        for (int j = 0; j < 16; j++) { acc[i][j] *= scale; m = fmaxf(m, acc[i][j]); }
#pragma unroll
        for (int off = 8; off > 0; off >>= 1)
            m = fmaxf(m, __shfl_xor_sync(0xffffffffu, m, off, 16));
        float s = 0.0f;
#pragma unroll
        for (int j = 0; j < 16; j++) { acc[i][j] = __expf(acc[i][j] - m); s += acc[i][j]; }
#pragma unroll
        for (int off = 8; off > 0; off >>= 1)
            s += __shfl_xor_sync(0xffffffffu, s, off, 16);
        float inv = 1.0f / s;
#pragma unroll
        for (int j = 0; j < 16; j++) acc[i][j] *= inv;
    }
    __syncthreads();   // phase-1 smem dead, safe to repurpose

    // ---- Phase 3: O = P * V ----
    float* Ps = sm;              // [256][65]  (s-major, padded)
    float* Vs = sm + 256 * 65;   // [16][256]
#pragma unroll
    for (int j = 0; j < 16; j++)
#pragma unroll
        for (int i = 0; i < 4; i++)
            Ps[(tx*16 + j) * 65 + ty*4 + i] = acc[i][j];
    __syncthreads();

    for (int h = 0; h < 2; h++) {
        float oa[4][16];
#pragma unroll
        for (int i = 0; i < 4; i++)
#pragma unroll
            for (int j = 0; j < 16; j++) oa[i][j] = 0.0f;

        for (int s0 = 0; s0 < S_; s0 += 16) {
#pragma unroll
            for (int i = 0; i < 4; i++) {
                int e  = tid + i * 256;      // float4 index 0..1023
                int r  = e >> 6;             // 0..15 row within tile
                int c4 = (e & 63) * 4;       // 0..252
                *(float4*)&Vs[r*256 + c4] =
                    *(const float4*)(Vb + (size_t)(s0 + r) * D_ + h * 256 + c4);
            }
            __syncthreads();

#pragma unroll
            for (int kk = 0; kk < 16; kk++) {
                float rp[4], rv[16];
                rp[0] = Ps[(s0+kk)*65 + ty*4 + 0];
                rp[1] = Ps[(s0+kk)*65 + ty*4 + 1];
                rp[2] = Ps[(s0+kk)*65 + ty*4 + 2];
                rp[3] = Ps[(s0+kk)*65 + ty*4 + 3];
                *(float4*)&rv[0]  = *(const float4*)&Vs[kk*256 + tx*16 + 0];
                *(float4*)&rv[4]  = *(const float4*)&Vs[kk*256 + tx*16 + 4];
                *(float4*)&rv[8]  = *(const float4*)&Vs[kk*256 + tx*16 + 8];
                *(float4*)&rv[12] = *(const float4*)&Vs[kk*256 + tx*16 + 12];
#pragma unroll
                for (int i = 0; i < 4; i++)
#pragma unroll
                    for (int j = 0; j < 16; j++)
                        oa[i][j] = fmaf(rp[i], rv[j], oa[i][j]);
            }
            __syncthreads();
        }

        float* ob = o + (size_t)bl * C_ * D_ + (size_t)(ct*64) * D_ + h * 256;
#pragma unroll
        for (int i = 0; i < 4; i++) {
#pragma unroll
            for (int j4 = 0; j4 < 4; j4++) {
                float4 w;
                w.x = oa[i][j4*4 + 0]; w.y = oa[i][j4*4 + 1];
                w.z = oa[i][j4*4 + 2]; w.w = oa[i][j4*4 + 3];
                *(float4*)(ob + (size_t)(ty*4 + i) * D_ + tx*16 + j4*4) = w;
            }
        }
    }
}

// ---------------------------------------------------------------------------
extern "C" void kernel_launch(void* const* d_in, const int* in_sizes, int n_in,
                              void* d_out, int out_size)
{
    (void)in_sizes; (void)n_in; (void)out_size;
    const float* queries = (const float*)d_in[0];
    const float* keys    = (const float*)d_in[1];
    const float* values  = (const float*)d_in[2];
    const float* Wq      = (const float*)d_in[3];
    const float* bq      = (const float*)d_in[4];
    const float* Wkv     = (const float*)d_in[5];
    const float* bkv     = (const float*)d_in[6];
    const float* Wo      = (const float*)d_in[7];
    const float* bo      = (const float*)d_in[8];
    float* out = (float*)d_out;

    float *p_q, *p_k, *p_v, *p_att;
    cudaGetSymbolAddress((void**)&p_q,   g_q);
    cudaGetSymbolAddress((void**)&p_k,   g_k);
    cudaGetSymbolAddress((void**)&p_v,   g_v);
    cudaGetSymbolAddress((void**)&p_att, g_att);

    const int attn_smem = (256 * 65 + 16 * 256) * (int)sizeof(float); // 82,944 B
    (void)cudaFuncSetAttribute(attn_kernel,
                               cudaFuncAttributeMaxDynamicSharedMemorySize,
                               attn_smem);

    dim3 gblk(256);
    dim3 ggrid(D_ / 128, NQ / 128);   // (4, 256)

    // Projections
    gemm_nt_bias<<<ggrid, gblk>>>(queries, Wq,  bq,  p_q, NQ, D_, D_);
    gemm_nt_bias<<<ggrid, gblk>>>(keys,    Wkv, bkv, p_k, NQ, D_, D_);
    gemm_nt_bias<<<ggrid, gblk>>>(values,  Wkv, bkv, p_v, NQ, D_, D_);

    // Attention: B*L * (C/64) = 512 blocks
    attn_kernel<<<B_ * L_ * (C_ / 64), 256, attn_smem>>>(p_q, p_k, p_v, p_att);

    // Output projection
    gemm_nt_bias<<<ggrid, gblk>>>(p_att, Wo, bo, out, NQ, D_, D_);
}

// round 3
// speedup vs baseline: 2.5248x; 2.5248x over previous
#include <cuda_runtime.h>
#include <math.h>
#include <stdint.h>

#define B_ 2
#define L_ 64
#define C_ 256
#define S_ 256
#define D_ 512
#define NQ (B_*L_*C_)   /* 32768 rows for q / k / v / att */

// Scratch (module-load allocated; no runtime allocs)
__device__ float g_q  [(size_t)NQ * D_];
__device__ float g_k  [(size_t)NQ * D_];
__device__ float g_v  [(size_t)NQ * D_];
__device__ float g_att[(size_t)NQ * D_];

// ---------------------------------------------------------------------------
// tf32 helpers
// ---------------------------------------------------------------------------
__device__ __forceinline__ uint32_t f2tf32(float f) {
    uint32_t u;
    asm("cvt.rna.tf32.f32 %0, %1;" : "=r"(u) : "f"(f));
    return u;
}

__device__ __forceinline__ void mma_tf32(float d[4], const uint32_t a[4],
                                         const uint32_t b[2]) {
    asm volatile(
        "mma.sync.aligned.m16n8k8.row.col.f32.tf32.tf32.f32 "
        "{%0,%1,%2,%3}, {%4,%5,%6,%7}, {%8,%9}, {%0,%1,%2,%3};\n"
        : "+f"(d[0]), "+f"(d[1]), "+f"(d[2]), "+f"(d[3])
        : "r"(a[0]), "r"(a[1]), "r"(a[2]), "r"(a[3]),
          "r"(b[0]), "r"(b[1]));
}

// ---------------------------------------------------------------------------
// NT GEMM with bias via tf32 tensor-core mma:
//   C[M,N] = A[M,K] * B[N,K]^T + bias[N]     (fp32 in/out, tf32 multiply)
// Block tile 128x128, BK=16, 256 threads = 8 warps (4 m x 2 n).
// Warp tile 32x64 = 2x8 m16n8k8 mma tiles.
// smem rows padded to stride 20 floats: fragment LDS pattern (g*20 + tig)
// touches 32 distinct banks -> conflict-free.
// ---------------------------------------------------------------------------
__global__ __launch_bounds__(256) void gemm_nt_tf32(
    const float* __restrict__ A, const float* __restrict__ Bm,
    const float* __restrict__ bias, float* __restrict__ C,
    int M, int N, int K)
{
    __shared__ uint32_t As[128 * 20];
    __shared__ uint32_t Bs[128 * 20];

    const int tid  = threadIdx.x;
    const int wid  = tid >> 5;
    const int lane = tid & 31;
    const int g    = lane >> 2;       // groupID 0..7
    const int tig  = lane & 3;        // thread-in-group 0..3

    const int wm = wid & 3;           // warp m index 0..3 (32 rows each)
    const int wn = wid >> 2;          // warp n index 0..1 (64 cols each)

    const int row0 = blockIdx.y * 128;
    const int col0 = blockIdx.x * 128;

    // gmem->smem mapping: thread handles row (tid>>1), k-half (tid&1)*8
    const int lrow = tid >> 1;        // 0..127
    const int kh   = (tid & 1) * 8;   // 0 or 8
    const float* Ap = A  + (size_t)(row0 + lrow) * K + kh;
    const float* Bp = Bm + (size_t)(col0 + lrow) * K + kh;

    float acc[2][8][4];
#pragma unroll
    for (int mt = 0; mt < 2; mt++)
#pragma unroll
        for (int nt = 0; nt < 8; nt++)
#pragma unroll
            for (int i = 0; i < 4; i++) acc[mt][nt][i] = 0.0f;

    // prologue loads
    float4 ra0 = *(const float4*)(Ap + 0);
    float4 ra1 = *(const float4*)(Ap + 4);
    float4 rb0 = *(const float4*)(Bp + 0);
    float4 rb1 = *(const float4*)(Bp + 4);

    for (int k0 = 0; k0 < K; k0 += 16) {
        // convert + store current tile
        {
            uint4 ua, ub;
            uint32_t* ap = As + lrow * 20 + kh;
            uint32_t* bp = Bs + lrow * 20 + kh;
            ua.x = f2tf32(ra0.x); ua.y = f2tf32(ra0.y);
            ua.z = f2tf32(ra0.z); ua.w = f2tf32(ra0.w);
            *(uint4*)(ap + 0) = ua;
            ua.x = f2tf32(ra1.x); ua.y = f2tf32(ra1.y);
            ua.z = f2tf32(ra1.z); ua.w = f2tf32(ra1.w);
            *(uint4*)(ap + 4) = ua;
            ub.x = f2tf32(rb0.x); ub.y = f2tf32(rb0.y);
            ub.z = f2tf32(rb0.z); ub.w = f2tf32(rb0.w);
            *(uint4*)(bp + 0) = ub;
            ub.x = f2tf32(rb1.x); ub.y = f2tf32(rb1.y);
            ub.z = f2tf32(rb1.z); ub.w = f2tf32(rb1.w);
            *(uint4*)(bp + 4) = ub;
        }
        __syncthreads();

        // prefetch next tile into registers (hidden under mma)
        if (k0 + 16 < K) {
            ra0 = *(const float4*)(Ap + k0 + 16);
            ra1 = *(const float4*)(Ap + k0 + 20);
            rb0 = *(const float4*)(Bp + k0 + 16);
            rb1 = *(const float4*)(Bp + k0 + 20);
        }

        // two k8 sub-steps
#pragma unroll
        for (int kk = 0; kk < 16; kk += 8) {
            uint32_t af[2][4];
            uint32_t bf[8][2];
#pragma unroll
            for (int mt = 0; mt < 2; mt++) {
                const int rb = wm * 32 + mt * 16;
                af[mt][0] = As[(rb + g    ) * 20 + kk + tig    ];
                af[mt][1] = As[(rb + g + 8) * 20 + kk + tig    ];
                af[mt][2] = As[(rb + g    ) * 20 + kk + tig + 4];
                af[mt][3] = As[(rb + g + 8) * 20 + kk + tig + 4];
            }
#pragma unroll
            for (int nt = 0; nt < 8; nt++) {
                const int cb = wn * 64 + nt * 8;
                bf[nt][0] = Bs[(cb + g) * 20 + kk + tig    ];
                bf[nt][1] = Bs[(cb + g) * 20 + kk + tig + 4];
            }
#pragma unroll
            for (int mt = 0; mt < 2; mt++)
#pragma unroll
                for (int nt = 0; nt < 8; nt++)
                    mma_tf32(acc[mt][nt], af[mt], bf[nt]);
        }
        __syncthreads();
    }

    // epilogue: bias + store (c0,c1 adjacent cols -> float2)
#pragma unroll
    for (int nt = 0; nt < 8; nt++) {
        const int col = col0 + wn * 64 + nt * 8 + tig * 2;
        const float bx = bias[col];
        const float by = bias[col + 1];
#pragma unroll
        for (int mt = 0; mt < 2; mt++) {
            const int r = row0 + wm * 32 + mt * 16 + g;
            float2 v0, v1;
            v0.x = acc[mt][nt][0] + bx; v0.y = acc[mt][nt][1] + by;
            v1.x = acc[mt][nt][2] + bx; v1.y = acc[mt][nt][3] + by;
            *(float2*)(C + (size_t)r * N + col)       = v0;
            *(float2*)(C + (size_t)(r + 8) * N + col) = v1;
        }
    }
}

// ---------------------------------------------------------------------------
// Attention (unchanged from passing R2 kernel): per block one (b,l) and a
// 64-row query tile. S = scale*Q*K^T, P = softmax(S), O = P*V.
// ---------------------------------------------------------------------------
__global__ __launch_bounds__(256) void attn_kernel(
    const float* __restrict__ q, const float* __restrict__ k,
    const float* __restrict__ v, float* __restrict__ o)
{
    extern __shared__ float sm[];
    const int tid = threadIdx.x;
    const int tx  = tid & 15;
    const int ty  = tid >> 4;
    const int bl  = blockIdx.x >> 2;   // 0..127 (b*l)
    const int ct  = blockIdx.x & 3;    // 0..3 query tile

    const float* Qb = q + (size_t)bl * C_ * D_ + (size_t)ct * 64 * D_;
    const float* Kb = k + (size_t)bl * S_ * D_;
    const float* Vb = v + (size_t)bl * S_ * D_;

    float acc[4][16];
#pragma unroll
    for (int i = 0; i < 4; i++)
#pragma unroll
        for (int j = 0; j < 16; j++) acc[i][j] = 0.0f;

    // ---- Phase 1: S = Q * K^T ----
    float* Qs = sm;             // [16][64]  k-major
    float* Ks = sm + 16 * 64;   // [16][256] k-major
    const int qr = tid >> 2;          // 0..63
    const int qk = (tid & 3) * 4;     // 0,4,8,12

    for (int k0 = 0; k0 < D_; k0 += 16) {
        float4 a = *(const float4*)(Qb + (size_t)qr * D_ + k0 + qk);
        Qs[(qk+0)*64 + qr] = a.x; Qs[(qk+1)*64 + qr] = a.y;
        Qs[(qk+2)*64 + qr] = a.z; Qs[(qk+3)*64 + qr] = a.w;
#pragma unroll
        for (int i = 0; i < 4; i++) {
            int r = qr + i * 64;
            float4 b = *(const float4*)(Kb + (size_t)r * D_ + k0 + qk);
            Ks[(qk+0)*256 + r] = b.x; Ks[(qk+1)*256 + r] = b.y;
            Ks[(qk+2)*256 + r] = b.z; Ks[(qk+3)*256 + r] = b.w;
        }
        __syncthreads();

#pragma unroll
        for (int kk = 0; kk < 16; kk++) {
            float rq[4], rk[16];
            rq[0] = Qs[kk*64 + ty*4 + 0];
            rq[1] = Qs[kk*64 + ty*4 + 1];
            rq[2] = Qs[kk*64 + ty*4 + 2];
            rq[3] = Qs[kk*64 + ty*4 + 3];
            *(float4*)&rk[0]  = *(const float4*)&Ks[kk*256 + tx*16 + 0];
            *(float4*)&rk[4]  = *(const float4*)&Ks[kk*256 + tx*16 + 4];
            *(float4*)&rk[8]  = *(const float4*)&Ks[kk*256 + tx*16 + 8];
            *(float4*)&rk[12] = *(const float4*)&Ks[kk*256 + tx*16 + 12];
#pragma unroll
            for (int i = 0; i < 4; i++)
#pragma unroll
                for (int j = 0; j < 16; j++)
                    acc[i][j] = fmaf(rq[i], rk[j], acc[i][j]);
        }
        __syncthreads();
    }

    // ---- Phase 2: softmax over rows ----
    const float scale = 0.04419417382415922f;   // 1/sqrt(512)
#pragma unroll
    for (int i = 0; i < 4; i++) {
        float m = -1e30f;
#pragma unroll
        for (int j = 0; j < 16; j++) { acc[i][j] *= scale; m = fmaxf(m, acc[i][j]); }
#pragma unroll
        for (int off = 8; off > 0; off >>= 1)
            m = fmaxf(m, __shfl_xor_sync(0xffffffffu, m, off, 16));
        float s = 0.0f;
#pragma unroll
        for (int j = 0; j < 16; j++) { acc[i][j] = __expf(acc[i][j] - m); s += acc[i][j]; }
#pragma unroll
        for (int off = 8; off > 0; off >>= 1)
            s += __shfl_xor_sync(0xffffffffu, s, off, 16);
        float inv = 1.0f / s;
#pragma unroll
        for (int j = 0; j < 16; j++) acc[i][j] *= inv;
    }
    __syncthreads();   // phase-1 smem dead, safe to repurpose

    // ---- Phase 3: O = P * V ----
    float* Ps = sm;              // [256][65]  (s-major, padded)
    float* Vs = sm + 256 * 65;   // [16][256]
#pragma unroll
    for (int j = 0; j < 16; j++)
#pragma unroll
        for (int i = 0; i < 4; i++)
            Ps[(tx*16 + j) * 65 + ty*4 + i] = acc[i][j];
    __syncthreads();

    for (int h = 0; h < 2; h++) {
        float oa[4][16];
#pragma unroll
        for (int i = 0; i < 4; i++)
#pragma unroll
            for (int j = 0; j < 16; j++) oa[i][j] = 0.0f;

        for (int s0 = 0; s0 < S_; s0 += 16) {
#pragma unroll
            for (int i = 0; i < 4; i++) {
                int e  = tid + i * 256;      // float4 index 0..1023
                int r  = e >> 6;             // 0..15 row within tile
                int c4 = (e & 63) * 4;       // 0..252
                *(float4*)&Vs[r*256 + c4] =
                    *(const float4*)(Vb + (size_t)(s0 + r) * D_ + h * 256 + c4);
            }
            __syncthreads();

#pragma unroll
            for (int kk = 0; kk < 16; kk++) {
                float rp[4], rv[16];
                rp[0] = Ps[(s0+kk)*65 + ty*4 + 0];
                rp[1] = Ps[(s0+kk)*65 + ty*4 + 1];
                rp[2] = Ps[(s0+kk)*65 + ty*4 + 2];
                rp[3] = Ps[(s0+kk)*65 + ty*4 + 3];
                *(float4*)&rv[0]  = *(const float4*)&Vs[kk*256 + tx*16 + 0];
                *(float4*)&rv[4]  = *(const float4*)&Vs[kk*256 + tx*16 + 4];
                *(float4*)&rv[8]  = *(const float4*)&Vs[kk*256 + tx*16 + 8];
                *(float4*)&rv[12] = *(const float4*)&Vs[kk*256 + tx*16 + 12];
#pragma unroll
                for (int i = 0; i < 4; i++)
#pragma unroll
                    for (int j = 0; j < 16; j++)
                        oa[i][j] = fmaf(rp[i], rv[j], oa[i][j]);
            }
            __syncthreads();
        }

        float* ob = o + (size_t)bl * C_ * D_ + (size_t)(ct*64) * D_ + h * 256;
#pragma unroll
        for (int i = 0; i < 4; i++) {
#pragma unroll
            for (int j4 = 0; j4 < 4; j4++) {
                float4 w;
                w.x = oa[i][j4*4 + 0]; w.y = oa[i][j4*4 + 1];
                w.z = oa[i][j4*4 + 2]; w.w = oa[i][j4*4 + 3];
                *(float4*)(ob + (size_t)(ty*4 + i) * D_ + tx*16 + j4*4) = w;
            }
        }
    }
}

// ---------------------------------------------------------------------------
extern "C" void kernel_launch(void* const* d_in, const int* in_sizes, int n_in,
                              void* d_out, int out_size)
{
    (void)in_sizes; (void)n_in; (void)out_size;
    const float* queries = (const float*)d_in[0];
    const float* keys    = (const float*)d_in[1];
    const float* values  = (const float*)d_in[2];
    const float* Wq      = (const float*)d_in[3];
    const float* bq      = (const float*)d_in[4];
    const float* Wkv     = (const float*)d_in[5];
    const float* bkv     = (const float*)d_in[6];
    const float* Wo      = (const float*)d_in[7];
    const float* bo      = (const float*)d_in[8];
    float* out = (float*)d_out;

    float *p_q, *p_k, *p_v, *p_att;
    cudaGetSymbolAddress((void**)&p_q,   g_q);
    cudaGetSymbolAddress((void**)&p_k,   g_k);
    cudaGetSymbolAddress((void**)&p_v,   g_v);
    cudaGetSymbolAddress((void**)&p_att, g_att);

    const int attn_smem = (256 * 65 + 16 * 256) * (int)sizeof(float); // 82,944 B
    (void)cudaFuncSetAttribute(attn_kernel,
                               cudaFuncAttributeMaxDynamicSharedMemorySize,
                               attn_smem);

    dim3 gblk(256);
    dim3 ggrid(D_ / 128, NQ / 128);   // (4, 256)

    // Projections (tf32 tensor cores)
    gemm_nt_tf32<<<ggrid, gblk>>>(queries, Wq,  bq,  p_q, NQ, D_, D_);
    gemm_nt_tf32<<<ggrid, gblk>>>(keys,    Wkv, bkv, p_k, NQ, D_, D_);
    gemm_nt_tf32<<<ggrid, gblk>>>(values,  Wkv, bkv, p_v, NQ, D_, D_);

    // Attention: B*L * (C/64) = 512 blocks
    attn_kernel<<<B_ * L_ * (C_ / 64), 256, attn_smem>>>(p_q, p_k, p_v, p_att);

    // Output projection (tf32 tensor cores)
    gemm_nt_tf32<<<ggrid, gblk>>>(p_att, Wo, bo, out, NQ, D_, D_);
}

// round 4
// speedup vs baseline: 4.1092x; 1.6276x over previous
#include <cuda_runtime.h>
#include <math.h>
#include <stdint.h>

#define B_ 2
#define L_ 64
#define C_ 256
#define S_ 256
#define D_ 512
#define NQ (B_*L_*C_)   /* 32768 rows for q / k / v / att */

// Scratch (module-load allocated; no runtime allocs)
__device__ float g_q  [(size_t)NQ * D_];
__device__ float g_k  [(size_t)NQ * D_];
__device__ float g_v  [(size_t)NQ * D_];
__device__ float g_att[(size_t)NQ * D_];

// ---------------------------------------------------------------------------
// tf32 helpers
// ---------------------------------------------------------------------------
__device__ __forceinline__ uint32_t f2tf32(float f) {
    uint32_t u;
    asm("cvt.rna.tf32.f32 %0, %1;" : "=r"(u) : "f"(f));
    return u;
}

__device__ __forceinline__ void mma_tf32(float d[4], const uint32_t a[4],
                                         const uint32_t b[2]) {
    asm volatile(
        "mma.sync.aligned.m16n8k8.row.col.f32.tf32.tf32.f32 "
        "{%0,%1,%2,%3}, {%4,%5,%6,%7}, {%8,%9}, {%0,%1,%2,%3};\n"
        : "+f"(d[0]), "+f"(d[1]), "+f"(d[2]), "+f"(d[3])
        : "r"(a[0]), "r"(a[1]), "r"(a[2]), "r"(a[3]),
          "r"(b[0]), "r"(b[1]));
}

// ---------------------------------------------------------------------------
// NT GEMM with bias via tf32 tensor-core mma (unchanged from R3, passing):
//   C[M,N] = A[M,K] * B[N,K]^T + bias[N]
// ---------------------------------------------------------------------------
__global__ __launch_bounds__(256) void gemm_nt_tf32(
    const float* __restrict__ A, const float* __restrict__ Bm,
    const float* __restrict__ bias, float* __restrict__ C,
    int M, int N, int K)
{
    __shared__ uint32_t As[128 * 20];
    __shared__ uint32_t Bs[128 * 20];

    const int tid  = threadIdx.x;
    const int wid  = tid >> 5;
    const int lane = tid & 31;
    const int g    = lane >> 2;
    const int tig  = lane & 3;

    const int wm = wid & 3;
    const int wn = wid >> 2;

    const int row0 = blockIdx.y * 128;
    const int col0 = blockIdx.x * 128;

    const int lrow = tid >> 1;
    const int kh   = (tid & 1) * 8;
    const float* Ap = A  + (size_t)(row0 + lrow) * K + kh;
    const float* Bp = Bm + (size_t)(col0 + lrow) * K + kh;

    float acc[2][8][4];
#pragma unroll
    for (int mt = 0; mt < 2; mt++)
#pragma unroll
        for (int nt = 0; nt < 8; nt++)
#pragma unroll
            for (int i = 0; i < 4; i++) acc[mt][nt][i] = 0.0f;

    float4 ra0 = *(const float4*)(Ap + 0);
    float4 ra1 = *(const float4*)(Ap + 4);
    float4 rb0 = *(const float4*)(Bp + 0);
    float4 rb1 = *(const float4*)(Bp + 4);

    for (int k0 = 0; k0 < K; k0 += 16) {
        {
            uint4 ua, ub;
            uint32_t* ap = As + lrow * 20 + kh;
            uint32_t* bp = Bs + lrow * 20 + kh;
            ua.x = f2tf32(ra0.x); ua.y = f2tf32(ra0.y);
            ua.z = f2tf32(ra0.z); ua.w = f2tf32(ra0.w);
            *(uint4*)(ap + 0) = ua;
            ua.x = f2tf32(ra1.x); ua.y = f2tf32(ra1.y);
            ua.z = f2tf32(ra1.z); ua.w = f2tf32(ra1.w);
            *(uint4*)(ap + 4) = ua;
            ub.x = f2tf32(rb0.x); ub.y = f2tf32(rb0.y);
            ub.z = f2tf32(rb0.z); ub.w = f2tf32(rb0.w);
            *(uint4*)(bp + 0) = ub;
            ub.x = f2tf32(rb1.x); ub.y = f2tf32(rb1.y);
            ub.z = f2tf32(rb1.z); ub.w = f2tf32(rb1.w);
            *(uint4*)(bp + 4) = ub;
        }
        __syncthreads();

        if (k0 + 16 < K) {
            ra0 = *(const float4*)(Ap + k0 + 16);
            ra1 = *(const float4*)(Ap + k0 + 20);
            rb0 = *(const float4*)(Bp + k0 + 16);
            rb1 = *(const float4*)(Bp + k0 + 20);
        }

#pragma unroll
        for (int kk = 0; kk < 16; kk += 8) {
            uint32_t af[2][4];
            uint32_t bf[8][2];
#pragma unroll
            for (int mt = 0; mt < 2; mt++) {
                const int rb = wm * 32 + mt * 16;
                af[mt][0] = As[(rb + g    ) * 20 + kk + tig    ];
                af[mt][1] = As[(rb + g + 8) * 20 + kk + tig    ];
                af[mt][2] = As[(rb + g    ) * 20 + kk + tig + 4];
                af[mt][3] = As[(rb + g + 8) * 20 + kk + tig + 4];
            }
#pragma unroll
            for (int nt = 0; nt < 8; nt++) {
                const int cb = wn * 64 + nt * 8;
                bf[nt][0] = Bs[(cb + g) * 20 + kk + tig    ];
                bf[nt][1] = Bs[(cb + g) * 20 + kk + tig + 4];
            }
#pragma unroll
            for (int mt = 0; mt < 2; mt++)
#pragma unroll
                for (int nt = 0; nt < 8; nt++)
                    mma_tf32(acc[mt][nt], af[mt], bf[nt]);
        }
        __syncthreads();
    }

#pragma unroll
    for (int nt = 0; nt < 8; nt++) {
        const int col = col0 + wn * 64 + nt * 8 + tig * 2;
        const float bx = bias[col];
        const float by = bias[col + 1];
#pragma unroll
        for (int mt = 0; mt < 2; mt++) {
            const int r = row0 + wm * 32 + mt * 16 + g;
            float2 v0, v1;
            v0.x = acc[mt][nt][0] + bx; v0.y = acc[mt][nt][1] + by;
            v1.x = acc[mt][nt][2] + bx; v1.y = acc[mt][nt][3] + by;
            *(float2*)(C + (size_t)r * N + col)       = v0;
            *(float2*)(C + (size_t)(r + 8) * N + col) = v1;
        }
    }
}

// ---------------------------------------------------------------------------
// Tensor-core attention. One block = one (b,l) pair + 64-query tile.
//   Phase 1: S = Q K^T  (3xTF32 split precision, K-dim 512)
//   Phase 2: row softmax of scale*S in smem (stride 261), convert to tf32
//   Phase 3: O = P V    (plain tf32, K-dim 256, two 256-wide d halves)
// 256 threads = 8 warps: 4 m-warps (16 q-rows each) x 2 n-warps.
// Dynamic smem layout (uint32 words):
//   phase 1: Qh[64*20] Ql[64*20] Kh[256*20] Kl[256*20]   (12800 words)
//   phase 2/3: P[64*261] at 0, Vs[256*21] at 16704       (22080 words)
// ---------------------------------------------------------------------------
#define P_STRIDE 261
#define V_STRIDE 21
#define VS_OFF   (64 * P_STRIDE)   /* 16704 */

__global__ __launch_bounds__(256) void attn_tc_kernel(
    const float* __restrict__ q, const float* __restrict__ k,
    const float* __restrict__ v, float* __restrict__ o)
{
    extern __shared__ uint32_t sm[];
    const int tid  = threadIdx.x;
    const int wid  = tid >> 5;
    const int lane = tid & 31;
    const int g    = lane >> 2;
    const int tig  = lane & 3;
    const int wm   = wid & 3;          // 4 m-warps * 16 rows
    const int wn   = wid >> 2;         // 2 n-warps

    const int bl = blockIdx.x >> 2;    // (b*l)
    const int ct = blockIdx.x & 3;     // 64-query tile

    const float* Qb = q + (size_t)bl * C_ * D_ + (size_t)ct * 64 * D_;
    const float* Kb = k + (size_t)bl * S_ * D_;
    const float* Vb = v + (size_t)bl * S_ * D_;

    // ---------------- Phase 1: S = Q K^T (3xTF32) ----------------
    uint32_t* Qh = sm;                 // 64*20
    uint32_t* Ql = Qh + 64 * 20;
    uint32_t* Kh = Ql + 64 * 20;       // 256*20
    uint32_t* Kl = Kh + 256 * 20;

    float acc[16][4];
#pragma unroll
    for (int nt = 0; nt < 16; nt++)
#pragma unroll
        for (int i = 0; i < 4; i++) acc[nt][i] = 0.0f;

    const int qrow = tid >> 2;          // 0..63
    const int kc   = (tid & 3) * 4;     // 0,4,8,12

    for (int k0 = 0; k0 < D_; k0 += 16) {
        // stage Q tile 64x16 (hi/lo)
        {
            float4 a = *(const float4*)(Qb + (size_t)qrow * D_ + k0 + kc);
            uint32_t hx = f2tf32(a.x), hy = f2tf32(a.y),
                     hz = f2tf32(a.z), hw = f2tf32(a.w);
            uint32_t* p = Qh + qrow * 20 + kc;
            p[0] = hx; p[1] = hy; p[2] = hz; p[3] = hw;
            uint32_t* pl = Ql + qrow * 20 + kc;
            pl[0] = f2tf32(a.x - __uint_as_float(hx));
            pl[1] = f2tf32(a.y - __uint_as_float(hy));
            pl[2] = f2tf32(a.z - __uint_as_float(hz));
            pl[3] = f2tf32(a.w - __uint_as_float(hw));
        }
        // stage K tile 256x16 (hi/lo)
#pragma unroll
        for (int i = 0; i < 4; i++) {
            int r = qrow + i * 64;
            float4 b = *(const float4*)(Kb + (size_t)r * D_ + k0 + kc);
            uint32_t hx = f2tf32(b.x), hy = f2tf32(b.y),
                     hz = f2tf32(b.z), hw = f2tf32(b.w);
            uint32_t* p = Kh + r * 20 + kc;
            p[0] = hx; p[1] = hy; p[2] = hz; p[3] = hw;
            uint32_t* pl = Kl + r * 20 + kc;
            pl[0] = f2tf32(b.x - __uint_as_float(hx));
            pl[1] = f2tf32(b.y - __uint_as_float(hy));
            pl[2] = f2tf32(b.z - __uint_as_float(hz));
            pl[3] = f2tf32(b.w - __uint_as_float(hw));
        }
        __syncthreads();

#pragma unroll
        for (int kk = 0; kk < 16; kk += 8) {
            const int rb = wm * 16;
            uint32_t ah[4], al[4];
            ah[0] = Qh[(rb + g    ) * 20 + kk + tig    ];
            ah[1] = Qh[(rb + g + 8) * 20 + kk + tig    ];
            ah[2] = Qh[(rb + g    ) * 20 + kk + tig + 4];
            ah[3] = Qh[(rb + g + 8) * 20 + kk + tig + 4];
            al[0] = Ql[(rb + g    ) * 20 + kk + tig    ];
            al[1] = Ql[(rb + g + 8) * 20 + kk + tig    ];
            al[2] = Ql[(rb + g    ) * 20 + kk + tig + 4];
            al[3] = Ql[(rb + g + 8) * 20 + kk + tig + 4];
#pragma unroll
            for (int nt = 0; nt < 16; nt++) {
                const int cb = wn * 128 + nt * 8;
                uint32_t bh[2], blo[2];
                bh[0]  = Kh[(cb + g) * 20 + kk + tig    ];
                bh[1]  = Kh[(cb + g) * 20 + kk + tig + 4];
                blo[0] = Kl[(cb + g) * 20 + kk + tig    ];
                blo[1] = Kl[(cb + g) * 20 + kk + tig + 4];
                mma_tf32(acc[nt], ah, blo);   // small terms first
                mma_tf32(acc[nt], al, bh);
                mma_tf32(acc[nt], ah, bh);
            }
        }
        __syncthreads();
    }

    // ---------------- write scaled S to P smem ----------------
    float* Pf = (float*)sm;
    const float scale = 0.04419417382415922f;   // 1/sqrt(512)
#pragma unroll
    for (int nt = 0; nt < 16; nt++) {
        const int col = wn * 128 + nt * 8 + tig * 2;
        const int r0  = wm * 16 + g;
        Pf[(r0    ) * P_STRIDE + col    ] = acc[nt][0] * scale;
        Pf[(r0    ) * P_STRIDE + col + 1] = acc[nt][1] * scale;
        Pf[(r0 + 8) * P_STRIDE + col    ] = acc[nt][2] * scale;
        Pf[(r0 + 8) * P_STRIDE + col + 1] = acc[nt][3] * scale;
    }
    __syncthreads();

    // ---------------- Phase 2: softmax + tf32 convert ----------------
    {
        const int row = tid >> 2;          // 0..63
        const int c0  = (tid & 3) * 64;
        float* rp = Pf + row * P_STRIDE + c0;
        float m = -1e30f;
#pragma unroll 16
        for (int j = 0; j < 64; j++) m = fmaxf(m, rp[j]);
        m = fmaxf(m, __shfl_xor_sync(0xffffffffu, m, 1, 4));
        m = fmaxf(m, __shfl_xor_sync(0xffffffffu, m, 2, 4));
        float s = 0.0f;
#pragma unroll 16
        for (int j = 0; j < 64; j++) { float e = __expf(rp[j] - m); rp[j] = e; s += e; }
        s += __shfl_xor_sync(0xffffffffu, s, 1, 4);
        s += __shfl_xor_sync(0xffffffffu, s, 2, 4);
        const float inv = 1.0f / s;
        uint32_t* ru = (uint32_t*)rp;
#pragma unroll 16
        for (int j = 0; j < 64; j++) ru[j] = f2tf32(rp[j] * inv);
    }
    __syncthreads();

    // ---------------- Phase 3: O = P V ----------------
    uint32_t* Pu = sm;
    uint32_t* Vs = sm + VS_OFF;     // 256 d-rows x stride 21 (s index)
    float* ob = o + (size_t)bl * C_ * D_ + (size_t)ct * 64 * D_;

    for (int h = 0; h < 2; h++) {
        float oacc[16][4];
#pragma unroll
        for (int nt = 0; nt < 16; nt++)
#pragma unroll
            for (int i = 0; i < 4; i++) oacc[nt][i] = 0.0f;

        for (int s0 = 0; s0 < S_; s0 += 16) {
            // stage V chunk transposed: Vs[d][s], d in half (256 wide)
#pragma unroll
            for (int i = 0; i < 4; i++) {
                int e  = tid + i * 256;
                int s  = e >> 6;             // 0..15
                int d4 = (e & 63) * 4;       // 0..252
                float4 vv = *(const float4*)(Vb + (size_t)(s0 + s) * D_ + h * 256 + d4);
                Vs[(d4 + 0) * V_STRIDE + s] = f2tf32(vv.x);
                Vs[(d4 + 1) * V_STRIDE + s] = f2tf32(vv.y);
                Vs[(d4 + 2) * V_STRIDE + s] = f2tf32(vv.z);
                Vs[(d4 + 3) * V_STRIDE + s] = f2tf32(vv.w);
            }
            __syncthreads();

#pragma unroll
            for (int kk = 0; kk < 16; kk += 8) {
                const int rb = wm * 16;
                uint32_t af[4];
                af[0] = Pu[(rb + g    ) * P_STRIDE + s0 + kk + tig    ];
                af[1] = Pu[(rb + g + 8) * P_STRIDE + s0 + kk + tig    ];
                af[2] = Pu[(rb + g    ) * P_STRIDE + s0 + kk + tig + 4];
                af[3] = Pu[(rb + g + 8) * P_STRIDE + s0 + kk + tig + 4];
#pragma unroll
                for (int nt = 0; nt < 16; nt++) {
                    const int cb = wn * 128 + nt * 8;
                    uint32_t bf[2];
                    bf[0] = Vs[(cb + g) * V_STRIDE + kk + tig    ];
                    bf[1] = Vs[(cb + g) * V_STRIDE + kk + tig + 4];
                    mma_tf32(oacc[nt], af, bf);
                }
            }
            __syncthreads();
        }

        // store O half
#pragma unroll
        for (int nt = 0; nt < 16; nt++) {
            const int col = h * 256 + wn * 128 + nt * 8 + tig * 2;
            const int r0  = wm * 16 + g;
            float2 v0, v1;
            v0.x = oacc[nt][0]; v0.y = oacc[nt][1];
            v1.x = oacc[nt][2]; v1.y = oacc[nt][3];
            *(float2*)(ob + (size_t)r0 * D_ + col)       = v0;
            *(float2*)(ob + (size_t)(r0 + 8) * D_ + col) = v1;
        }
    }
}

// ---------------------------------------------------------------------------
extern "C" void kernel_launch(void* const* d_in, const int* in_sizes, int n_in,
                              void* d_out, int out_size)
{
    (void)in_sizes; (void)n_in; (void)out_size;
    const float* queries = (const float*)d_in[0];
    const float* keys    = (const float*)d_in[1];
    const float* values  = (const float*)d_in[2];
    const float* Wq      = (const float*)d_in[3];
    const float* bq      = (const float*)d_in[4];
    const float* Wkv     = (const float*)d_in[5];
    const float* bkv     = (const float*)d_in[6];
    const float* Wo      = (const float*)d_in[7];
    const float* bo      = (const float*)d_in[8];
    float* out = (float*)d_out;

    float *p_q, *p_k, *p_v, *p_att;
    cudaGetSymbolAddress((void**)&p_q,   g_q);
    cudaGetSymbolAddress((void**)&p_k,   g_k);
    cudaGetSymbolAddress((void**)&p_v,   g_v);
    cudaGetSymbolAddress((void**)&p_att, g_att);

    const int attn_smem = (64 * P_STRIDE + 256 * V_STRIDE) * (int)sizeof(uint32_t); // 88320
    (void)cudaFuncSetAttribute(attn_tc_kernel,
                               cudaFuncAttributeMaxDynamicSharedMemorySize,
                               attn_smem);

    dim3 gblk(256);
    dim3 ggrid(D_ / 128, NQ / 128);   // (4, 256)

    // Projections (tf32 tensor cores)
    gemm_nt_tf32<<<ggrid, gblk>>>(queries, Wq,  bq,  p_q, NQ, D_, D_);
    gemm_nt_tf32<<<ggrid, gblk>>>(keys,    Wkv, bkv, p_k, NQ, D_, D_);
    gemm_nt_tf32<<<ggrid, gblk>>>(values,  Wkv, bkv, p_v, NQ, D_, D_);

    // Attention: 512 blocks (tensor cores)
    attn_tc_kernel<<<B_ * L_ * (C_ / 64), 256, attn_smem>>>(p_q, p_k, p_v, p_att);

    // Output projection (tf32 tensor cores)
    gemm_nt_tf32<<<ggrid, gblk>>>(p_att, Wo, bo, out, NQ, D_, D_);
}

// round 5
// speedup vs baseline: 4.2927x; 1.0447x over previous
#include <cuda_runtime.h>
#include <math.h>
#include <stdint.h>

#define B_ 2
#define L_ 64
#define C_ 256
#define S_ 256
#define D_ 512
#define NQ (B_*L_*C_)   /* 32768 rows for q / k / v / att */

// Scratch (module-load allocated; no runtime allocs)
__device__ float g_q  [(size_t)NQ * D_];
__device__ float g_k  [(size_t)NQ * D_];
__device__ float g_v  [(size_t)NQ * D_];
__device__ float g_att[(size_t)NQ * D_];

// ---------------------------------------------------------------------------
// tf32 helpers
// ---------------------------------------------------------------------------
__device__ __forceinline__ uint32_t f2tf32(float f) {
    uint32_t u;
    asm("cvt.rna.tf32.f32 %0, %1;" : "=r"(u) : "f"(f));
    return u;
}

__device__ __forceinline__ void mma_tf32(float d[4], const uint32_t a[4],
                                         const uint32_t b[2]) {
    asm volatile(
        "mma.sync.aligned.m16n8k8.row.col.f32.tf32.tf32.f32 "
        "{%0,%1,%2,%3}, {%4,%5,%6,%7}, {%8,%9}, {%0,%1,%2,%3};\n"
        : "+f"(d[0]), "+f"(d[1]), "+f"(d[2]), "+f"(d[3])
        : "r"(a[0]), "r"(a[1]), "r"(a[2]), "r"(a[3]),
          "r"(b[0]), "r"(b[1]));
}

// ---------------------------------------------------------------------------
// NT GEMM with bias, tf32 mma, DOUBLE-BUFFERED smem (one sync per k-iter).
//   C[M,N] = A[M,K] * B[N,K]^T + bias[N], K = 512 fixed.
// Block tile 128x128, BK=16, 256 threads = 8 warps (4m x 2n).
// ---------------------------------------------------------------------------
#define GK 512
#define GNIT (GK/16)

__global__ __launch_bounds__(256) void gemm_nt_tf32(
    const float* __restrict__ A, const float* __restrict__ Bm,
    const float* __restrict__ bias, float* __restrict__ C,
    int M, int N)
{
    __shared__ uint32_t As[2][128 * 20];
    __shared__ uint32_t Bs[2][128 * 20];

    const int tid  = threadIdx.x;
    const int wid  = tid >> 5;
    const int lane = tid & 31;
    const int g    = lane >> 2;
    const int tig  = lane & 3;

    const int wm = wid & 3;
    const int wn = wid >> 2;

    const int row0 = blockIdx.y * 128;
    const int col0 = blockIdx.x * 128;

    const int lrow = tid >> 1;
    const int kh   = (tid & 1) * 8;
    const float* Ap = A  + (size_t)(row0 + lrow) * GK + kh;
    const float* Bp = Bm + (size_t)(col0 + lrow) * GK + kh;

    float acc[2][8][4];
#pragma unroll
    for (int mt = 0; mt < 2; mt++)
#pragma unroll
        for (int nt = 0; nt < 8; nt++)
#pragma unroll
            for (int i = 0; i < 4; i++) acc[mt][nt][i] = 0.0f;

    // prologue: tile0 -> buf0; tile1 -> regs (pending)
    float4 ra0, ra1, rb0, rb1;
    {
        ra0 = *(const float4*)(Ap + 0);
        ra1 = *(const float4*)(Ap + 4);
        rb0 = *(const float4*)(Bp + 0);
        rb1 = *(const float4*)(Bp + 4);
        uint4 u;
        uint32_t* ap = As[0] + lrow * 20 + kh;
        uint32_t* bp = Bs[0] + lrow * 20 + kh;
        u.x = f2tf32(ra0.x); u.y = f2tf32(ra0.y); u.z = f2tf32(ra0.z); u.w = f2tf32(ra0.w);
        *(uint4*)(ap + 0) = u;
        u.x = f2tf32(ra1.x); u.y = f2tf32(ra1.y); u.z = f2tf32(ra1.z); u.w = f2tf32(ra1.w);
        *(uint4*)(ap + 4) = u;
        u.x = f2tf32(rb0.x); u.y = f2tf32(rb0.y); u.z = f2tf32(rb0.z); u.w = f2tf32(rb0.w);
        *(uint4*)(bp + 0) = u;
        u.x = f2tf32(rb1.x); u.y = f2tf32(rb1.y); u.z = f2tf32(rb1.z); u.w = f2tf32(rb1.w);
        *(uint4*)(bp + 4) = u;
        ra0 = *(const float4*)(Ap + 16);
        ra1 = *(const float4*)(Ap + 20);
        rb0 = *(const float4*)(Bp + 16);
        rb1 = *(const float4*)(Bp + 20);
    }
    __syncthreads();

#pragma unroll 2
    for (int it = 0; it < GNIT; it++) {
        const int cur = it & 1;
        // store pending tile (it+1) into the other buffer
        if (it + 1 < GNIT) {
            uint4 u;
            uint32_t* ap = As[cur ^ 1] + lrow * 20 + kh;
            uint32_t* bp = Bs[cur ^ 1] + lrow * 20 + kh;
            u.x = f2tf32(ra0.x); u.y = f2tf32(ra0.y); u.z = f2tf32(ra0.z); u.w = f2tf32(ra0.w);
            *(uint4*)(ap + 0) = u;
            u.x = f2tf32(ra1.x); u.y = f2tf32(ra1.y); u.z = f2tf32(ra1.z); u.w = f2tf32(ra1.w);
            *(uint4*)(ap + 4) = u;
            u.x = f2tf32(rb0.x); u.y = f2tf32(rb0.y); u.z = f2tf32(rb0.z); u.w = f2tf32(rb0.w);
            *(uint4*)(bp + 0) = u;
            u.x = f2tf32(rb1.x); u.y = f2tf32(rb1.y); u.z = f2tf32(rb1.z); u.w = f2tf32(rb1.w);
            *(uint4*)(bp + 4) = u;
        }
        // prefetch tile (it+2) into regs
        if (it + 2 < GNIT) {
            const int k2 = (it + 2) * 16;
            ra0 = *(const float4*)(Ap + k2 + 0);
            ra1 = *(const float4*)(Ap + k2 + 4);
            rb0 = *(const float4*)(Bp + k2 + 0);
            rb1 = *(const float4*)(Bp + k2 + 4);
        }

        // MMA on buffer cur
#pragma unroll
        for (int kk = 0; kk < 16; kk += 8) {
            uint32_t af[2][4];
            uint32_t bf[8][2];
#pragma unroll
            for (int mt = 0; mt < 2; mt++) {
                const int rb = wm * 32 + mt * 16;
                af[mt][0] = As[cur][(rb + g    ) * 20 + kk + tig    ];
                af[mt][1] = As[cur][(rb + g + 8) * 20 + kk + tig    ];
                af[mt][2] = As[cur][(rb + g    ) * 20 + kk + tig + 4];
                af[mt][3] = As[cur][(rb + g + 8) * 20 + kk + tig + 4];
            }
#pragma unroll
            for (int nt = 0; nt < 8; nt++) {
                const int cb = wn * 64 + nt * 8;
                bf[nt][0] = Bs[cur][(cb + g) * 20 + kk + tig    ];
                bf[nt][1] = Bs[cur][(cb + g) * 20 + kk + tig + 4];
            }
#pragma unroll
            for (int mt = 0; mt < 2; mt++)
#pragma unroll
                for (int nt = 0; nt < 8; nt++)
                    mma_tf32(acc[mt][nt], af[mt], bf[nt]);
        }
        __syncthreads();
    }

#pragma unroll
    for (int nt = 0; nt < 8; nt++) {
        const int col = col0 + wn * 64 + nt * 8 + tig * 2;
        const float bx = bias[col];
        const float by = bias[col + 1];
#pragma unroll
        for (int mt = 0; mt < 2; mt++) {
            const int r = row0 + wm * 32 + mt * 16 + g;
            float2 v0, v1;
            v0.x = acc[mt][nt][0] + bx; v0.y = acc[mt][nt][1] + by;
            v1.x = acc[mt][nt][2] + bx; v1.y = acc[mt][nt][3] + by;
            *(float2*)(C + (size_t)r * N + col)       = v0;
            *(float2*)(C + (size_t)(r + 8) * N + col) = v1;
        }
    }
}

// ---------------------------------------------------------------------------
// Tensor-core attention, phase-1 double-buffered.
// Dynamic smem (uint32 words):
//   phase 1: two buffers of [Qh 1280 | Ql 1280 | Kh 5120 | Kl 5120] = 12800
//            -> 25600 words
//   phase 2/3: P[64*261] at 0, Vs[256*21] at 16704 -> 22080 words
//   allocation = 25600 words = 102,400 B
// ---------------------------------------------------------------------------
#define P_STRIDE 261
#define V_STRIDE 21
#define VS_OFF   (64 * P_STRIDE)   /* 16704 */
#define P1BUF    12800

__global__ __launch_bounds__(256) void attn_tc_kernel(
    const float* __restrict__ q, const float* __restrict__ k,
    const float* __restrict__ v, float* __restrict__ o)
{
    extern __shared__ uint32_t sm[];
    const int tid  = threadIdx.x;
    const int wid  = tid >> 5;
    const int lane = tid & 31;
    const int g    = lane >> 2;
    const int tig  = lane & 3;
    const int wm   = wid & 3;
    const int wn   = wid >> 2;

    const int bl = blockIdx.x >> 2;
    const int ct = blockIdx.x & 3;

    const float* Qb = q + (size_t)bl * C_ * D_ + (size_t)ct * 64 * D_;
    const float* Kb = k + (size_t)bl * S_ * D_;
    const float* Vb = v + (size_t)bl * S_ * D_;

    float acc[16][4];
#pragma unroll
    for (int nt = 0; nt < 16; nt++)
#pragma unroll
        for (int i = 0; i < 4; i++) acc[nt][i] = 0.0f;

    const int qrow = tid >> 2;          // 0..63
    const int kc   = (tid & 3) * 4;     // 0,4,8,12

    // ---------------- Phase 1: S = Q K^T (3xTF32, double-buffered) --------
    // stage tile `it` (k0 = it*16) into buffer b
    auto stage = [&](int it, int b) {
        uint32_t* Qh = sm + b * P1BUF;
        uint32_t* Ql = Qh + 1280;
        uint32_t* Kh = Ql + 1280;
        uint32_t* Kl = Kh + 5120;
        const int k0 = it * 16;
        {
            float4 a = *(const float4*)(Qb + (size_t)qrow * D_ + k0 + kc);
            uint32_t hx = f2tf32(a.x), hy = f2tf32(a.y),
                     hz = f2tf32(a.z), hw = f2tf32(a.w);
            uint32_t* p = Qh + qrow * 20 + kc;
            p[0] = hx; p[1] = hy; p[2] = hz; p[3] = hw;
            uint32_t* pl = Ql + qrow * 20 + kc;
            pl[0] = f2tf32(a.x - __uint_as_float(hx));
            pl[1] = f2tf32(a.y - __uint_as_float(hy));
            pl[2] = f2tf32(a.z - __uint_as_float(hz));
            pl[3] = f2tf32(a.w - __uint_as_float(hw));
        }
#pragma unroll
        for (int i = 0; i < 4; i++) {
            int r = qrow + i * 64;
            float4 bb = *(const float4*)(Kb + (size_t)r * D_ + k0 + kc);
            uint32_t hx = f2tf32(bb.x), hy = f2tf32(bb.y),
                     hz = f2tf32(bb.z), hw = f2tf32(bb.w);
            uint32_t* p = Kh + r * 20 + kc;
            p[0] = hx; p[1] = hy; p[2] = hz; p[3] = hw;
            uint32_t* pl = Kl + r * 20 + kc;
            pl[0] = f2tf32(bb.x - __uint_as_float(hx));
            pl[1] = f2tf32(bb.y - __uint_as_float(hy));
            pl[2] = f2tf32(bb.z - __uint_as_float(hz));
            pl[3] = f2tf32(bb.w - __uint_as_float(hw));
        }
    };

    stage(0, 0);
    __syncthreads();

    for (int it = 0; it < D_ / 16; it++) {
        const int cur = it & 1;
        if (it + 1 < D_ / 16) stage(it + 1, cur ^ 1);

        const uint32_t* Qh = sm + cur * P1BUF;
        const uint32_t* Ql = Qh + 1280;
        const uint32_t* Kh = Ql + 1280;
        const uint32_t* Kl = Kh + 5120;

#pragma unroll
        for (int kk = 0; kk < 16; kk += 8) {
            const int rb = wm * 16;
            uint32_t ah[4], al[4];
            ah[0] = Qh[(rb + g    ) * 20 + kk + tig    ];
            ah[1] = Qh[(rb + g + 8) * 20 + kk + tig    ];
            ah[2] = Qh[(rb + g    ) * 20 + kk + tig + 4];
            ah[3] = Qh[(rb + g + 8) * 20 + kk + tig + 4];
            al[0] = Ql[(rb + g    ) * 20 + kk + tig    ];
            al[1] = Ql[(rb + g + 8) * 20 + kk + tig    ];
            al[2] = Ql[(rb + g    ) * 20 + kk + tig + 4];
            al[3] = Ql[(rb + g + 8) * 20 + kk + tig + 4];
#pragma unroll
            for (int nt = 0; nt < 16; nt++) {
                const int cb = wn * 128 + nt * 8;
                uint32_t bh[2], blo[2];
                bh[0]  = Kh[(cb + g) * 20 + kk + tig    ];
                bh[1]  = Kh[(cb + g) * 20 + kk + tig + 4];
                blo[0] = Kl[(cb + g) * 20 + kk + tig    ];
                blo[1] = Kl[(cb + g) * 20 + kk + tig + 4];
                mma_tf32(acc[nt], ah, blo);
                mma_tf32(acc[nt], al, bh);
                mma_tf32(acc[nt], ah, bh);
            }
        }
        __syncthreads();
    }

    // ---------------- write scaled S to P smem ----------------
    float* Pf = (float*)sm;
    const float scale = 0.04419417382415922f;   // 1/sqrt(512)
#pragma unroll
    for (int nt = 0; nt < 16; nt++) {
        const int col = wn * 128 + nt * 8 + tig * 2;
        const int r0  = wm * 16 + g;
        Pf[(r0    ) * P_STRIDE + col    ] = acc[nt][0] * scale;
        Pf[(r0    ) * P_STRIDE + col + 1] = acc[nt][1] * scale;
        Pf[(r0 + 8) * P_STRIDE + col    ] = acc[nt][2] * scale;
        Pf[(r0 + 8) * P_STRIDE + col + 1] = acc[nt][3] * scale;
    }
    __syncthreads();

    // ---------------- Phase 2: softmax + tf32 convert ----------------
    {
        const int row = tid >> 2;
        const int c0  = (tid & 3) * 64;
        float* rp = Pf + row * P_STRIDE + c0;
        float m = -1e30f;
#pragma unroll 16
        for (int j = 0; j < 64; j++) m = fmaxf(m, rp[j]);
        m = fmaxf(m, __shfl_xor_sync(0xffffffffu, m, 1, 4));
        m = fmaxf(m, __shfl_xor_sync(0xffffffffu, m, 2, 4));
        float s = 0.0f;
#pragma unroll 16
        for (int j = 0; j < 64; j++) { float e = __expf(rp[j] - m); rp[j] = e; s += e; }
        s += __shfl_xor_sync(0xffffffffu, s, 1, 4);
        s += __shfl_xor_sync(0xffffffffu, s, 2, 4);
        const float inv = 1.0f / s;
        uint32_t* ru = (uint32_t*)rp;
#pragma unroll 16
        for (int j = 0; j < 64; j++) ru[j] = f2tf32(rp[j] * inv);
    }
    __syncthreads();

    // ---------------- Phase 3: O = P V ----------------
    uint32_t* Pu = sm;
    uint32_t* Vs = sm + VS_OFF;
    float* ob = o + (size_t)bl * C_ * D_ + (size_t)ct * 64 * D_;

    for (int h = 0; h < 2; h++) {
        float oacc[16][4];
#pragma unroll
        for (int nt = 0; nt < 16; nt++)
#pragma unroll
            for (int i = 0; i < 4; i++) oacc[nt][i] = 0.0f;

        for (int s0 = 0; s0 < S_; s0 += 16) {
#pragma unroll
            for (int i = 0; i < 4; i++) {
                int e  = tid + i * 256;
                int s  = e >> 6;
                int d4 = (e & 63) * 4;
                float4 vv = *(const float4*)(Vb + (size_t)(s0 + s) * D_ + h * 256 + d4);
                Vs[(d4 + 0) * V_STRIDE + s] = f2tf32(vv.x);
                Vs[(d4 + 1) * V_STRIDE + s] = f2tf32(vv.y);
                Vs[(d4 + 2) * V_STRIDE + s] = f2tf32(vv.z);
                Vs[(d4 + 3) * V_STRIDE + s] = f2tf32(vv.w);
            }
            __syncthreads();

#pragma unroll
            for (int kk = 0; kk < 16; kk += 8) {
                const int rb = wm * 16;
                uint32_t af[4];
                af[0] = Pu[(rb + g    ) * P_STRIDE + s0 + kk + tig    ];
                af[1] = Pu[(rb + g + 8) * P_STRIDE + s0 + kk + tig    ];
                af[2] = Pu[(rb + g    ) * P_STRIDE + s0 + kk + tig + 4];
                af[3] = Pu[(rb + g + 8) * P_STRIDE + s0 + kk + tig + 4];
#pragma unroll
                for (int nt = 0; nt < 16; nt++) {
                    const int cb = wn * 128 + nt * 8;
                    uint32_t bf[2];
                    bf[0] = Vs[(cb + g) * V_STRIDE + kk + tig    ];
                    bf[1] = Vs[(cb + g) * V_STRIDE + kk + tig + 4];
                    mma_tf32(oacc[nt], af, bf);
                }
            }
            __syncthreads();
        }

#pragma unroll
        for (int nt = 0; nt < 16; nt++) {
            const int col = h * 256 + wn * 128 + nt * 8 + tig * 2;
            const int r0  = wm * 16 + g;
            float2 v0, v1;
            v0.x = oacc[nt][0]; v0.y = oacc[nt][1];
            v1.x = oacc[nt][2]; v1.y = oacc[nt][3];
            *(float2*)(ob + (size_t)r0 * D_ + col)       = v0;
            *(float2*)(ob + (size_t)(r0 + 8) * D_ + col) = v1;
        }
    }
}

// ---------------------------------------------------------------------------
extern "C" void kernel_launch(void* const* d_in, const int* in_sizes, int n_in,
                              void* d_out, int out_size)
{
    (void)in_sizes; (void)n_in; (void)out_size;
    const float* queries = (const float*)d_in[0];
    const float* keys    = (const float*)d_in[1];
    const float* values  = (const float*)d_in[2];
    const float* Wq      = (const float*)d_in[3];
    const float* bq      = (const float*)d_in[4];
    const float* Wkv     = (const float*)d_in[5];
    const float* bkv     = (const float*)d_in[6];
    const float* Wo      = (const float*)d_in[7];
    const float* bo      = (const float*)d_in[8];
    float* out = (float*)d_out;

    float *p_q, *p_k, *p_v, *p_att;
    cudaGetSymbolAddress((void**)&p_q,   g_q);
    cudaGetSymbolAddress((void**)&p_k,   g_k);
    cudaGetSymbolAddress((void**)&p_v,   g_v);
    cudaGetSymbolAddress((void**)&p_att, g_att);

    const int attn_smem = 2 * P1BUF * (int)sizeof(uint32_t);   // 102,400 B
    (void)cudaFuncSetAttribute(attn_tc_kernel,
                               cudaFuncAttributeMaxDynamicSharedMemorySize,
                               attn_smem);

    dim3 gblk(256);
    dim3 ggrid(D_ / 128, NQ / 128);   // (4, 256)

    // Projections (tf32 tensor cores, double-buffered)
    gemm_nt_tf32<<<ggrid, gblk>>>(queries, Wq,  bq,  p_q, NQ, D_);
    gemm_nt_tf32<<<ggrid, gblk>>>(keys,    Wkv, bkv, p_k, NQ, D_);
    gemm_nt_tf32<<<ggrid, gblk>>>(values,  Wkv, bkv, p_v, NQ, D_);

    // Attention: 512 blocks (tensor cores)
    attn_tc_kernel<<<B_ * L_ * (C_ / 64), 256, attn_smem>>>(p_q, p_k, p_v, p_att);

    // Output projection (tf32 tensor cores, double-buffered)
    gemm_nt_tf32<<<ggrid, gblk>>>(p_att, Wo, bo, out, NQ, D_);
}

// round 7
// speedup vs baseline: 4.5523x; 1.0605x over previous
#include <cuda_runtime.h>
#include <math.h>
#include <stdint.h>

#define B_ 2
#define L_ 64
#define C_ 256
#define S_ 256
#define D_ 512
#define NQ (B_*L_*C_)   /* 32768 rows */

// Scratch (module-load allocated; no runtime allocs)
__device__ float g_q  [(size_t)NQ * D_];
__device__ float g_k  [(size_t)NQ * D_];
__device__ float g_v  [(size_t)NQ * D_];
__device__ float g_att[(size_t)NQ * D_];

// ---------------------------------------------------------------------------
// helpers
// ---------------------------------------------------------------------------
__device__ __forceinline__ uint32_t smem_u32(const void* p) {
    uint32_t a;
    asm("{ .reg .u64 t; cvta.to.shared.u64 t, %1; cvt.u32.u64 %0, t; }"
        : "=r"(a) : "l"(p));
    return a;
}
__device__ __forceinline__ uint32_t f2tf32(float f) {
    uint32_t u;
    asm("cvt.rna.tf32.f32 %0, %1;" : "=r"(u) : "f"(f));
    return u;
}
__device__ __forceinline__ void mma_tf32(float d[4], const uint32_t a[4],
                                         const uint32_t b[2]) {
    asm volatile(
        "mma.sync.aligned.m16n8k8.row.col.f32.tf32.tf32.f32 "
        "{%0,%1,%2,%3}, {%4,%5,%6,%7}, {%8,%9}, {%0,%1,%2,%3};\n"
        : "+f"(d[0]), "+f"(d[1]), "+f"(d[2]), "+f"(d[3])
        : "r"(a[0]), "r"(a[1]), "r"(a[2]), "r"(a[3]),
          "r"(b[0]), "r"(b[1]));
}
// one ldmatrix.x4: 4 8x8(16B-row) tiles -> 4 regs
__device__ __forceinline__ void ldsm_x4(uint32_t r[4], uint32_t addr) {
    asm volatile("ldmatrix.sync.aligned.m8n8.x4.shared.b16 {%0,%1,%2,%3}, [%4];"
        : "=r"(r[0]), "=r"(r[1]), "=r"(r[2]), "=r"(r[3]) : "r"(addr));
}

// ---------------------------------------------------------------------------
// NT GEMM with bias, tf32 mma, double-buffered smem, ldmatrix operand loads.
//   C[M,N] = A[M,512] * B[N,512]^T + bias[N]
// 128x128 tile, BK=16, 256 threads = 8 warps (4m x 2n), warp tile 32x64.
// ---------------------------------------------------------------------------
#define GK 512
#define GNIT (GK/16)

__global__ __launch_bounds__(256) void gemm_nt_tf32(
    const float* __restrict__ A, const float* __restrict__ Bm,
    const float* __restrict__ bias, float* __restrict__ C,
    int M, int N)
{
    __shared__ uint32_t As[2][128 * 20];
    __shared__ uint32_t Bs[2][128 * 20];

    const int tid  = threadIdx.x;
    const int wid  = tid >> 5;
    const int lane = tid & 31;
    const int g    = lane >> 2;
    const int tig  = lane & 3;

    const int wm = wid & 3;
    const int wn = wid >> 2;

    const int row0 = blockIdx.y * 128;
    const int col0 = blockIdx.x * 128;

    const int lrow = tid >> 1;
    const int kh   = (tid & 1) * 8;
    const float* Ap = A  + (size_t)(row0 + lrow) * GK + kh;
    const float* Bp = Bm + (size_t)(col0 + lrow) * GK + kh;

    // ldmatrix base byte-offsets (within one buffer)
    const uint32_t asb0 = smem_u32(As[0]);
    const uint32_t bsb0 = smem_u32(Bs[0]);
    const uint32_t aoff = 4u * ((wm * 32 + (lane & 15)) * 20 + (lane >> 4) * 4);
    const uint32_t boff = 4u * ((wn * 64 + ((lane >> 4) << 3) + (lane & 7)) * 20
                                + ((lane >> 3) & 1) * 4);

    float acc[2][8][4];
#pragma unroll
    for (int mt = 0; mt < 2; mt++)
#pragma unroll
        for (int nt = 0; nt < 8; nt++)
#pragma unroll
            for (int i = 0; i < 4; i++) acc[mt][nt][i] = 0.0f;

    float4 ra0, ra1, rb0, rb1;
    {
        ra0 = *(const float4*)(Ap + 0);
        ra1 = *(const float4*)(Ap + 4);
        rb0 = *(const float4*)(Bp + 0);
        rb1 = *(const float4*)(Bp + 4);
        uint4 u;
        uint32_t* ap = As[0] + lrow * 20 + kh;
        uint32_t* bp = Bs[0] + lrow * 20 + kh;
        u.x = f2tf32(ra0.x); u.y = f2tf32(ra0.y); u.z = f2tf32(ra0.z); u.w = f2tf32(ra0.w);
        *(uint4*)(ap + 0) = u;
        u.x = f2tf32(ra1.x); u.y = f2tf32(ra1.y); u.z = f2tf32(ra1.z); u.w = f2tf32(ra1.w);
        *(uint4*)(ap + 4) = u;
        u.x = f2tf32(rb0.x); u.y = f2tf32(rb0.y); u.z = f2tf32(rb0.z); u.w = f2tf32(rb0.w);
        *(uint4*)(bp + 0) = u;
        u.x = f2tf32(rb1.x); u.y = f2tf32(rb1.y); u.z = f2tf32(rb1.z); u.w = f2tf32(rb1.w);
        *(uint4*)(bp + 4) = u;
        ra0 = *(const float4*)(Ap + 16);
        ra1 = *(const float4*)(Ap + 20);
        rb0 = *(const float4*)(Bp + 16);
        rb1 = *(const float4*)(Bp + 20);
    }
    __syncthreads();

#pragma unroll 2
    for (int it = 0; it < GNIT; it++) {
        const int cur = it & 1;
        if (it + 1 < GNIT) {
            uint4 u;
            uint32_t* ap = As[cur ^ 1] + lrow * 20 + kh;
            uint32_t* bp = Bs[cur ^ 1] + lrow * 20 + kh;
            u.x = f2tf32(ra0.x); u.y = f2tf32(ra0.y); u.z = f2tf32(ra0.z); u.w = f2tf32(ra0.w);
            *(uint4*)(ap + 0) = u;
            u.x = f2tf32(ra1.x); u.y = f2tf32(ra1.y); u.z = f2tf32(ra1.z); u.w = f2tf32(ra1.w);
            *(uint4*)(ap + 4) = u;
            u.x = f2tf32(rb0.x); u.y = f2tf32(rb0.y); u.z = f2tf32(rb0.z); u.w = f2tf32(rb0.w);
            *(uint4*)(bp + 0) = u;
            u.x = f2tf32(rb1.x); u.y = f2tf32(rb1.y); u.z = f2tf32(rb1.z); u.w = f2tf32(rb1.w);
            *(uint4*)(bp + 4) = u;
        }
        if (it + 2 < GNIT) {
            const int k2 = (it + 2) * 16;
            ra0 = *(const float4*)(Ap + k2 + 0);
            ra1 = *(const float4*)(Ap + k2 + 4);
            rb0 = *(const float4*)(Bp + k2 + 0);
            rb1 = *(const float4*)(Bp + k2 + 4);
        }

        const uint32_t ab = asb0 + (uint32_t)cur * (128 * 20 * 4) + aoff;
        const uint32_t bb = bsb0 + (uint32_t)cur * (128 * 20 * 4) + boff;
#pragma unroll
        for (int kk = 0; kk < 16; kk += 8) {
            uint32_t af[2][4];
            ldsm_x4(af[0], ab + kk * 4);
            ldsm_x4(af[1], ab + 1280 + kk * 4);        // +16 rows * 20 w * 4B
            uint32_t bf[4][4];
#pragma unroll
            for (int p = 0; p < 4; p++)
                ldsm_x4(bf[p], bb + (uint32_t)p * 1280 + kk * 4);
#pragma unroll
            for (int mt = 0; mt < 2; mt++)
#pragma unroll
                for (int p = 0; p < 4; p++) {
                    mma_tf32(acc[mt][2*p    ], af[mt], &bf[p][0]);
                    mma_tf32(acc[mt][2*p + 1], af[mt], &bf[p][2]);
                }
        }
        __syncthreads();
    }

#pragma unroll
    for (int nt = 0; nt < 8; nt++) {
        const int col = col0 + wn * 64 + nt * 8 + tig * 2;
        const float bx = bias[col];
        const float by = bias[col + 1];
#pragma unroll
        for (int mt = 0; mt < 2; mt++) {
            const int r = row0 + wm * 32 + mt * 16 + g;
            float2 v0, v1;
            v0.x = acc[mt][nt][0] + bx; v0.y = acc[mt][nt][1] + by;
            v1.x = acc[mt][nt][2] + bx; v1.y = acc[mt][nt][3] + by;
            *(float2*)(C + (size_t)r * N + col)       = v0;
            *(float2*)(C + (size_t)(r + 8) * N + col) = v1;
        }
    }
}

// ---------------------------------------------------------------------------
// Tensor-core attention with ldmatrix operand loads.
// Dynamic smem (uint32 words):
//   phase 1: two buffers [Qh 1280 | Ql 1280 | Kh 5120 | Kl 5120] = 12800 each
//   phase 2/3: P[64*260] at 0, Vs[256*20] at 16640
//   allocation = 25600 words = 102,400 B
// ---------------------------------------------------------------------------
#define P_STRIDE 260
#define V_STRIDE 20
#define VS_OFF   (64 * P_STRIDE)   /* 16640 */
#define P1BUF    12800

__global__ __launch_bounds__(256) void attn_tc_kernel(
    const float* __restrict__ q, const float* __restrict__ k,
    const float* __restrict__ v, float* __restrict__ o)
{
    extern __shared__ uint32_t sm[];
    const int tid  = threadIdx.x;
    const int wid  = tid >> 5;
    const int lane = tid & 31;
    const int g    = lane >> 2;
    const int tig  = lane & 3;
    const int wm   = wid & 3;
    const int wn   = wid >> 2;

    const int bl = blockIdx.x >> 2;
    const int ct = blockIdx.x & 3;

    const float* Qb = q + (size_t)bl * C_ * D_ + (size_t)ct * 64 * D_;
    const float* Kb = k + (size_t)bl * S_ * D_;
    const float* Vb = v + (size_t)bl * S_ * D_;

    const uint32_t smb = smem_u32(sm);
    // ldmatrix per-lane offsets
    const uint32_t a20 = 4u * ((wm * 16 + (lane & 15)) * 20 + (lane >> 4) * 4);
    const uint32_t b20 = 4u * ((((lane >> 4) << 3) + (lane & 7)) * 20
                               + ((lane >> 3) & 1) * 4);

    float acc[16][4];
#pragma unroll
    for (int nt = 0; nt < 16; nt++)
#pragma unroll
        for (int i = 0; i < 4; i++) acc[nt][i] = 0.0f;

    const int qrow = tid >> 2;
    const int kc   = (tid & 3) * 4;

    auto stage = [&](int it, int b) {
        uint32_t* Qh = sm + b * P1BUF;
        uint32_t* Ql = Qh + 1280;
        uint32_t* Kh = Ql + 1280;
        uint32_t* Kl = Kh + 5120;
        const int k0 = it * 16;
        {
            float4 a = *(const float4*)(Qb + (size_t)qrow * D_ + k0 + kc);
            uint32_t hx = f2tf32(a.x), hy = f2tf32(a.y),
                     hz = f2tf32(a.z), hw = f2tf32(a.w);
            uint32_t* p = Qh + qrow * 20 + kc;
            p[0] = hx; p[1] = hy; p[2] = hz; p[3] = hw;
            uint32_t* pl = Ql + qrow * 20 + kc;
            pl[0] = f2tf32(a.x - __uint_as_float(hx));
            pl[1] = f2tf32(a.y - __uint_as_float(hy));
            pl[2] = f2tf32(a.z - __uint_as_float(hz));
            pl[3] = f2tf32(a.w - __uint_as_float(hw));
        }
#pragma unroll
        for (int i = 0; i < 4; i++) {
            int r = qrow + i * 64;
            float4 bb = *(const float4*)(Kb + (size_t)r * D_ + k0 + kc);
            uint32_t hx = f2tf32(bb.x), hy = f2tf32(bb.y),
                     hz = f2tf32(bb.z), hw = f2tf32(bb.w);
            uint32_t* p = Kh + r * 20 + kc;
            p[0] = hx; p[1] = hy; p[2] = hz; p[3] = hw;
            uint32_t* pl = Kl + r * 20 + kc;
            pl[0] = f2tf32(bb.x - __uint_as_float(hx));
            pl[1] = f2tf32(bb.y - __uint_as_float(hy));
            pl[2] = f2tf32(bb.z - __uint_as_float(hz));
            pl[3] = f2tf32(bb.w - __uint_as_float(hw));
        }
    };

    stage(0, 0);
    __syncthreads();

    for (int it = 0; it < D_ / 16; it++) {
        const int cur = it & 1;
        if (it + 1 < D_ / 16) stage(it + 1, cur ^ 1);

        const uint32_t bufb = smb + (uint32_t)cur * (P1BUF * 4);
        const uint32_t qh_a = bufb + a20;                    // Qh
        const uint32_t ql_a = bufb + 1280 * 4 + a20;         // Ql
        const uint32_t kh_b = bufb + 2560 * 4 + wn * 128 * 20 * 4 + b20;  // Kh
        const uint32_t kl_b = bufb + 7680 * 4 + wn * 128 * 20 * 4 + b20;  // Kl

#pragma unroll
        for (int kk = 0; kk < 16; kk += 8) {
            uint32_t ah[4], al[4];
            ldsm_x4(ah, qh_a + kk * 4);
            ldsm_x4(al, ql_a + kk * 4);
#pragma unroll
            for (int p = 0; p < 8; p++) {
                uint32_t bh[4], blo[4];
                ldsm_x4(bh,  kh_b + (uint32_t)p * 1280 + kk * 4);
                ldsm_x4(blo, kl_b + (uint32_t)p * 1280 + kk * 4);
                mma_tf32(acc[2*p    ], ah, &blo[0]);
                mma_tf32(acc[2*p    ], al, &bh[0]);
                mma_tf32(acc[2*p    ], ah, &bh[0]);
                mma_tf32(acc[2*p + 1], ah, &blo[2]);
                mma_tf32(acc[2*p + 1], al, &bh[2]);
                mma_tf32(acc[2*p + 1], ah, &bh[2]);
            }
        }
        __syncthreads();
    }

    // ---------------- write scaled S to P smem ----------------
    float* Pf = (float*)sm;
    const float scale = 0.04419417382415922f;
#pragma unroll
    for (int nt = 0; nt < 16; nt++) {
        const int col = wn * 128 + nt * 8 + tig * 2;
        const int r0  = wm * 16 + g;
        Pf[(r0    ) * P_STRIDE + col    ] = acc[nt][0] * scale;
        Pf[(r0    ) * P_STRIDE + col + 1] = acc[nt][1] * scale;
        Pf[(r0 + 8) * P_STRIDE + col    ] = acc[nt][2] * scale;
        Pf[(r0 + 8) * P_STRIDE + col + 1] = acc[nt][3] * scale;
    }
    __syncthreads();

    // ---------------- softmax + tf32 convert ----------------
    {
        const int row = tid >> 2;
        const int c0  = (tid & 3) * 64;
        float* rp = Pf + row * P_STRIDE + c0;
        float m = -1e30f;
#pragma unroll 16
        for (int j = 0; j < 64; j++) m = fmaxf(m, rp[j]);
        m = fmaxf(m, __shfl_xor_sync(0xffffffffu, m, 1, 4));
        m = fmaxf(m, __shfl_xor_sync(0xffffffffu, m, 2, 4));
        float s = 0.0f;
#pragma unroll 16
        for (int j = 0; j < 64; j++) { float e = __expf(rp[j] - m); rp[j] = e; s += e; }
        s += __shfl_xor_sync(0xffffffffu, s, 1, 4);
        s += __shfl_xor_sync(0xffffffffu, s, 2, 4);
        const float inv = 1.0f / s;
        uint32_t* ru = (uint32_t*)rp;
#pragma unroll 16
        for (int j = 0; j < 64; j++) ru[j] = f2tf32(rp[j] * inv);
    }
    __syncthreads();

    // ---------------- Phase 3: O = P V ----------------
    uint32_t* Vs = sm + VS_OFF;
    const uint32_t vsb = smb + VS_OFF * 4;
    const uint32_t p_a = smb + 4u * ((wm * 16 + (lane & 15)) * P_STRIDE
                                     + (lane >> 4) * 4);
    const uint32_t v_b = vsb + wn * 128 * 20 * 4 + b20;
    float* ob = o + (size_t)bl * C_ * D_ + (size_t)ct * 64 * D_;

    for (int h = 0; h < 2; h++) {
        float oacc[16][4];
#pragma unroll
        for (int nt = 0; nt < 16; nt++)
#pragma unroll
            for (int i = 0; i < 4; i++) oacc[nt][i] = 0.0f;

        for (int s0 = 0; s0 < S_; s0 += 16) {
#pragma unroll
            for (int i = 0; i < 4; i++) {
                int e  = tid + i * 256;
                int s  = e >> 6;
                int d4 = (e & 63) * 4;
                float4 vv = *(const float4*)(Vb + (size_t)(s0 + s) * D_ + h * 256 + d4);
                Vs[(d4 + 0) * V_STRIDE + s] = f2tf32(vv.x);
                Vs[(d4 + 1) * V_STRIDE + s] = f2tf32(vv.y);
                Vs[(d4 + 2) * V_STRIDE + s] = f2tf32(vv.z);
                Vs[(d4 + 3) * V_STRIDE + s] = f2tf32(vv.w);
            }
            __syncthreads();

#pragma unroll
            for (int kk = 0; kk < 16; kk += 8) {
                uint32_t af[4];
                ldsm_x4(af, p_a + (s0 + kk) * 4);
#pragma unroll
                for (int p = 0; p < 8; p++) {
                    uint32_t bf[4];
                    ldsm_x4(bf, v_b + (uint32_t)p * 1280 + kk * 4);
                    mma_tf32(oacc[2*p    ], af, &bf[0]);
                    mma_tf32(oacc[2*p + 1], af, &bf[2]);
                }
            }
            __syncthreads();
        }

#pragma unroll
        for (int nt = 0; nt < 16; nt++) {
            const int col = h * 256 + wn * 128 + nt * 8 + tig * 2;
            const int r0  = wm * 16 + g;
            float2 v0, v1;
            v0.x = oacc[nt][0]; v0.y = oacc[nt][1];
            v1.x = oacc[nt][2]; v1.y = oacc[nt][3];
            *(float2*)(ob + (size_t)r0 * D_ + col)       = v0;
            *(float2*)(ob + (size_t)(r0 + 8) * D_ + col) = v1;
        }
    }
}

// ---------------------------------------------------------------------------
extern "C" void kernel_launch(void* const* d_in, const int* in_sizes, int n_in,
                              void* d_out, int out_size)
{
    (void)in_sizes; (void)n_in; (void)out_size;
    const float* queries = (const float*)d_in[0];
    const float* keys    = (const float*)d_in[1];
    const float* values  = (const float*)d_in[2];
    const float* Wq      = (const float*)d_in[3];
    const float* bq      = (const float*)d_in[4];
    const float* Wkv     = (const float*)d_in[5];
    const float* bkv     = (const float*)d_in[6];
    const float* Wo      = (const float*)d_in[7];
    const float* bo      = (const float*)d_in[8];
    float* out = (float*)d_out;

    float *p_q, *p_k, *p_v, *p_att;
    cudaGetSymbolAddress((void**)&p_q,   g_q);
    cudaGetSymbolAddress((void**)&p_k,   g_k);
    cudaGetSymbolAddress((void**)&p_v,   g_v);
    cudaGetSymbolAddress((void**)&p_att, g_att);

    const int attn_smem = 2 * P1BUF * (int)sizeof(uint32_t);   // 102,400 B
    (void)cudaFuncSetAttribute(attn_tc_kernel,
                               cudaFuncAttributeMaxDynamicSharedMemorySize,
                               attn_smem);

    dim3 gblk(256);
    dim3 ggrid(D_ / 128, NQ / 128);   // (4, 256)

    gemm_nt_tf32<<<ggrid, gblk>>>(queries, Wq,  bq,  p_q, NQ, D_);
    gemm_nt_tf32<<<ggrid, gblk>>>(keys,    Wkv, bkv, p_k, NQ, D_);
    gemm_nt_tf32<<<ggrid, gblk>>>(values,  Wkv, bkv, p_v, NQ, D_);

    attn_tc_kernel<<<B_ * L_ * (C_ / 64), 256, attn_smem>>>(p_q, p_k, p_v, p_att);

    gemm_nt_tf32<<<ggrid, gblk>>>(p_att, Wo, bo, out, NQ, D_);
}

// round 9
// speedup vs baseline: 6.1251x; 1.3455x over previous
#include <cuda_runtime.h>
#include <cuda_fp16.h>
#include <math.h>
#include <stdint.h>

#define B_ 2
#define L_ 64
#define C_ 256
#define S_ 256
#define D_ 512
#define NQ (B_*L_*C_)   /* 32768 rows */

// Scratch (module-load allocated; no runtime allocs)
__device__ float g_q  [(size_t)NQ * D_];
__device__ float g_k  [(size_t)NQ * D_];
__device__ float g_v  [(size_t)NQ * D_];
__device__ float g_att[(size_t)NQ * D_];

// ---------------------------------------------------------------------------
// helpers
// ---------------------------------------------------------------------------
__device__ __forceinline__ uint32_t smem_u32(const void* p) {
    uint32_t a;
    asm("{ .reg .u64 t; cvta.to.shared.u64 t, %1; cvt.u32.u64 %0, t; }"
        : "=r"(a) : "l"(p));
    return a;
}
__device__ __forceinline__ uint32_t pack_h2(float a, float b) {
    __half2 h = __floats2half2_rn(a, b);
    return *(uint32_t*)&h;
}
// fp16 hi/lo split of two floats -> packed hi, packed lo
__device__ __forceinline__ void split2h(float a, float b, uint32_t& h, uint32_t& l) {
    __half ha = __float2half_rn(a);
    __half hb = __float2half_rn(b);
    __half la = __float2half_rn(a - __half2float(ha));
    __half lb = __float2half_rn(b - __half2float(hb));
    __half2 hp = __halves2half2(ha, hb);
    __half2 lp = __halves2half2(la, lb);
    h = *(uint32_t*)&hp;
    l = *(uint32_t*)&lp;
}
__device__ __forceinline__ void mma_f16(float d[4], const uint32_t a[4],
                                        const uint32_t b[2]) {
    asm volatile(
        "mma.sync.aligned.m16n8k16.row.col.f32.f16.f16.f32 "
        "{%0,%1,%2,%3}, {%4,%5,%6,%7}, {%8,%9}, {%0,%1,%2,%3};\n"
        : "+f"(d[0]), "+f"(d[1]), "+f"(d[2]), "+f"(d[3])
        : "r"(a[0]), "r"(a[1]), "r"(a[2]), "r"(a[3]),
          "r"(b[0]), "r"(b[1]));
}
__device__ __forceinline__ void ldsm_x4(uint32_t r[4], uint32_t addr) {
    asm volatile("ldmatrix.sync.aligned.m8n8.x4.shared.b16 {%0,%1,%2,%3}, [%4];"
        : "=r"(r[0]), "=r"(r[1]), "=r"(r[2]), "=r"(r[3]) : "r"(addr));
}

// ---------------------------------------------------------------------------
// NT GEMM with bias, fp16 m16n8k16 mma, double-buffered smem, ldmatrix.
//   C[M,N] = A[M,512] * B[N,512]^T + bias[N]
// 128x128 tile, BK=16, 256 threads = 8 warps (4m x 2n), warp tile 32x64.
// smem rows: 16 halves padded to 24 (48B) -> conflict-free ldmatrix.
// ---------------------------------------------------------------------------
#define GK 512
#define GNIT (GK/16)

__global__ __launch_bounds__(256) void gemm_nt_f16(
    const float* __restrict__ A, const float* __restrict__ Bm,
    const float* __restrict__ bias, float* __restrict__ C,
    int M, int N)
{
    __shared__ __half As[2][128 * 24];
    __shared__ __half Bs[2][128 * 24];

    const int tid  = threadIdx.x;
    const int wid  = tid >> 5;
    const int lane = tid & 31;
    const int g    = lane >> 2;
    const int tig  = lane & 3;

    const int wm = wid & 3;
    const int wn = wid >> 2;

    const int row0 = blockIdx.y * 128;
    const int col0 = blockIdx.x * 128;

    const int lrow = tid >> 1;          // 0..127
    const int kh   = (tid & 1) * 8;     // 0 or 8
    const float* Ap = A  + (size_t)(row0 + lrow) * GK + kh;
    const float* Bp = Bm + (size_t)(col0 + lrow) * GK + kh;

    const uint32_t asb = smem_u32(As[0]);
    const uint32_t bsb = smem_u32(Bs[0]);
    const uint32_t aoff = (uint32_t)((wm * 32 + (lane & 15)) * 48 + (lane >> 4) * 16);
    const uint32_t boff = (uint32_t)((wn * 64 + ((lane >> 4) << 3) + (lane & 7)) * 48
                                     + ((lane >> 3) & 1) * 16);

    float acc[2][8][4];
#pragma unroll
    for (int mt = 0; mt < 2; mt++)
#pragma unroll
        for (int nt = 0; nt < 8; nt++)
#pragma unroll
            for (int i = 0; i < 4; i++) acc[mt][nt][i] = 0.0f;

    float4 ra0, ra1, rb0, rb1;
    // prologue: tile0 -> buf0, tile1 -> regs
    {
        ra0 = *(const float4*)(Ap + 0);
        ra1 = *(const float4*)(Ap + 4);
        rb0 = *(const float4*)(Bp + 0);
        rb1 = *(const float4*)(Bp + 4);
        uint4 u;
        u.x = pack_h2(ra0.x, ra0.y); u.y = pack_h2(ra0.z, ra0.w);
        u.z = pack_h2(ra1.x, ra1.y); u.w = pack_h2(ra1.z, ra1.w);
        *(uint4*)&As[0][lrow * 24 + kh] = u;
        u.x = pack_h2(rb0.x, rb0.y); u.y = pack_h2(rb0.z, rb0.w);
        u.z = pack_h2(rb1.x, rb1.y); u.w = pack_h2(rb1.z, rb1.w);
        *(uint4*)&Bs[0][lrow * 24 + kh] = u;
        ra0 = *(const float4*)(Ap + 16);
        ra1 = *(const float4*)(Ap + 20);
        rb0 = *(const float4*)(Bp + 16);
        rb1 = *(const float4*)(Bp + 20);
    }
    __syncthreads();

#pragma unroll 2
    for (int it = 0; it < GNIT; it++) {
        const int cur = it & 1;
        if (it + 1 < GNIT) {
            uint4 u;
            u.x = pack_h2(ra0.x, ra0.y); u.y = pack_h2(ra0.z, ra0.w);
            u.z = pack_h2(ra1.x, ra1.y); u.w = pack_h2(ra1.z, ra1.w);
            *(uint4*)&As[cur ^ 1][lrow * 24 + kh] = u;
            u.x = pack_h2(rb0.x, rb0.y); u.y = pack_h2(rb0.z, rb0.w);
            u.z = pack_h2(rb1.x, rb1.y); u.w = pack_h2(rb1.z, rb1.w);
            *(uint4*)&Bs[cur ^ 1][lrow * 24 + kh] = u;
        }
        if (it + 2 < GNIT) {
            const int k2 = (it + 2) * 16;
            ra0 = *(const float4*)(Ap + k2 + 0);
            ra1 = *(const float4*)(Ap + k2 + 4);
            rb0 = *(const float4*)(Bp + k2 + 0);
            rb1 = *(const float4*)(Bp + k2 + 4);
        }

        const uint32_t ab = asb + (uint32_t)cur * (128 * 24 * 2) + aoff;
        const uint32_t bb = bsb + (uint32_t)cur * (128 * 24 * 2) + boff;
        uint32_t af[2][4];
        ldsm_x4(af[0], ab);
        ldsm_x4(af[1], ab + 768);          // +16 rows * 48B
        uint32_t bf[4][4];
#pragma unroll
        for (int p = 0; p < 4; p++)
            ldsm_x4(bf[p], bb + (uint32_t)p * 768);
#pragma unroll
        for (int mt = 0; mt < 2; mt++)
#pragma unroll
            for (int p = 0; p < 4; p++) {
                mma_f16(acc[mt][2*p    ], af[mt], &bf[p][0]);
                mma_f16(acc[mt][2*p + 1], af[mt], &bf[p][2]);
            }
        __syncthreads();
    }

#pragma unroll
    for (int nt = 0; nt < 8; nt++) {
        const int col = col0 + wn * 64 + nt * 8 + tig * 2;
        const float bx = bias[col];
        const float by = bias[col + 1];
#pragma unroll
        for (int mt = 0; mt < 2; mt++) {
            const int r = row0 + wm * 32 + mt * 16 + g;
            float2 v0, v1;
            v0.x = acc[mt][nt][0] + bx; v0.y = acc[mt][nt][1] + by;
            v1.x = acc[mt][nt][2] + bx; v1.y = acc[mt][nt][3] + by;
            *(float2*)(C + (size_t)r * N + col)       = v0;
            *(float2*)(C + (size_t)(r + 8) * N + col) = v1;
        }
    }
}

// ---------------------------------------------------------------------------
// fp16 tensor-core attention. One block = (b,l) + 64-query tile.
//  P1: S = Q K^T, fp16 3-term hi/lo split at k16 (error ~2^-21)
//  P2: register softmax (cross-warp reduce via 1KB smem), write plain fp16 P
//  P3: O = P V, plain fp16 k16 (error class == previous tf32 k8)
// smem bytes:
//  P1: 2 buffers of [Qh 3072 | Ql 3072 | Kh 12288 | Kl 12288] = 30720 each
//  P3: Ph[64 x 264h] at 0 (33792B), Vh[256 x 24h] at 33792 (12288B)
//  RED: redmax 64x2 f32 at 61440, redsum at 61952; total 62464B
// ---------------------------------------------------------------------------
#define P1_BUF   30720
#define QH_O     0
#define QL_O     3072
#define KH_O     6144
#define KL_O     18432
#define PH_O     0
#define P_ROW_B  528          /* 264 halves */
#define VH_O     33792
#define RED_O    61440
#define ATTN_SMEM 62464

__global__ __launch_bounds__(256) void attn_f16_kernel(
    const float* __restrict__ q, const float* __restrict__ k,
    const float* __restrict__ v, float* __restrict__ o)
{
    extern __shared__ char smc[];
    const int tid  = threadIdx.x;
    const int wid  = tid >> 5;
    const int lane = tid & 31;
    const int g    = lane >> 2;
    const int tig  = lane & 3;
    const int wm   = wid & 3;          // 4 m-warps x 16 q-rows
    const int wn   = wid >> 2;         // 2 n-warps x 128 cols

    const int bl = blockIdx.x >> 2;
    const int ct = blockIdx.x & 3;

    const float* Qb = q + (size_t)bl * C_ * D_ + (size_t)ct * 64 * D_;
    const float* Kb = k + (size_t)bl * S_ * D_;
    const float* Vb = v + (size_t)bl * S_ * D_;

    const uint32_t smb = smem_u32(smc);
    // ldmatrix per-lane byte offsets
    const uint32_t qa  = (uint32_t)((wm * 16 + (lane & 15)) * 48 + (lane >> 4) * 16);
    const uint32_t kb_ = (uint32_t)((wn * 128 + ((lane >> 4) << 3) + (lane & 7)) * 48
                                    + ((lane >> 3) & 1) * 16);
    const uint32_t pa  = (uint32_t)((wm * 16 + (lane & 15)) * P_ROW_B + (lane >> 4) * 16);

    float acc[16][4];
#pragma unroll
    for (int nt = 0; nt < 16; nt++)
#pragma unroll
        for (int i = 0; i < 4; i++) acc[nt][i] = 0.0f;

    const int qrow = tid >> 2;          // 0..63
    const int kc   = (tid & 3) * 4;     // 0,4,8,12

    // ---------------- Phase 1: S = Q K^T ----------------
    auto stage = [&](int it, int b) {
        char* base = smc + b * P1_BUF;
        const int k0 = it * 16;
        {
            float4 a = *(const float4*)(Qb + (size_t)qrow * D_ + k0 + kc);
            uint32_t h0, l0, h1, l1;
            split2h(a.x, a.y, h0, l0);
            split2h(a.z, a.w, h1, l1);
            *(uint2*)(base + QH_O + qrow * 48 + kc * 2) = make_uint2(h0, h1);
            *(uint2*)(base + QL_O + qrow * 48 + kc * 2) = make_uint2(l0, l1);
        }
#pragma unroll
        for (int i = 0; i < 4; i++) {
            const int r = qrow + i * 64;
            float4 bb = *(const float4*)(Kb + (size_t)r * D_ + k0 + kc);
            uint32_t h0, l0, h1, l1;
            split2h(bb.x, bb.y, h0, l0);
            split2h(bb.z, bb.w, h1, l1);
            *(uint2*)(base + KH_O + r * 48 + kc * 2) = make_uint2(h0, h1);
            *(uint2*)(base + KL_O + r * 48 + kc * 2) = make_uint2(l0, l1);
        }
    };

    stage(0, 0);
    __syncthreads();

    for (int it = 0; it < D_ / 16; it++) {
        const int cur = it & 1;
        if (it + 1 < D_ / 16) stage(it + 1, cur ^ 1);

        const uint32_t bufb = smb + (uint32_t)cur * P1_BUF;
        uint32_t ah[4], al[4];
        ldsm_x4(ah, bufb + QH_O + qa);
        ldsm_x4(al, bufb + QL_O + qa);
#pragma unroll
        for (int p = 0; p < 8; p++) {
            uint32_t bh[4], blo[4];
            ldsm_x4(bh,  bufb + KH_O + kb_ + (uint32_t)p * 768);
            ldsm_x4(blo, bufb + KL_O + kb_ + (uint32_t)p * 768);
            mma_f16(acc[2*p    ], ah, &blo[0]);
            mma_f16(acc[2*p    ], al, &bh[0]);
            mma_f16(acc[2*p    ], ah, &bh[0]);
            mma_f16(acc[2*p + 1], ah, &blo[2]);
            mma_f16(acc[2*p + 1], al, &bh[2]);
            mma_f16(acc[2*p + 1], ah, &bh[2]);
        }
        __syncthreads();
    }

    // ---------------- Phase 2: register softmax ----------------
    {
        float* redm = (float*)(smc + RED_O);          // 64 x 2
        float* reds = redm + 128;                     // 64 x 2
        const float scale = 0.04419417382415922f;     // 1/sqrt(512)
        const int r0 = wm * 16 + g;

        float mx0 = -1e30f, mx1 = -1e30f;
#pragma unroll
        for (int nt = 0; nt < 16; nt++) {
            acc[nt][0] *= scale; acc[nt][1] *= scale;
            acc[nt][2] *= scale; acc[nt][3] *= scale;
            mx0 = fmaxf(mx0, fmaxf(acc[nt][0], acc[nt][1]));
            mx1 = fmaxf(mx1, fmaxf(acc[nt][2], acc[nt][3]));
        }
        mx0 = fmaxf(mx0, __shfl_xor_sync(0xffffffffu, mx0, 1));
        mx0 = fmaxf(mx0, __shfl_xor_sync(0xffffffffu, mx0, 2));
        mx1 = fmaxf(mx1, __shfl_xor_sync(0xffffffffu, mx1, 1));
        mx1 = fmaxf(mx1, __shfl_xor_sync(0xffffffffu, mx1, 2));
        if (tig == 0) { redm[r0 * 2 + wn] = mx0; redm[(r0 + 8) * 2 + wn] = mx1; }
        __syncthreads();
        const float m0 = fmaxf(redm[r0 * 2], redm[r0 * 2 + 1]);
        const float m1 = fmaxf(redm[(r0 + 8) * 2], redm[(r0 + 8) * 2 + 1]);

        float s0 = 0.0f, s1 = 0.0f;
#pragma unroll
        for (int nt = 0; nt < 16; nt++) {
            acc[nt][0] = __expf(acc[nt][0] - m0); s0 += acc[nt][0];
            acc[nt][1] = __expf(acc[nt][1] - m0); s0 += acc[nt][1];
            acc[nt][2] = __expf(acc[nt][2] - m1); s1 += acc[nt][2];
            acc[nt][3] = __expf(acc[nt][3] - m1); s1 += acc[nt][3];
        }
        s0 += __shfl_xor_sync(0xffffffffu, s0, 1);
        s0 += __shfl_xor_sync(0xffffffffu, s0, 2);
        s1 += __shfl_xor_sync(0xffffffffu, s1, 1);
        s1 += __shfl_xor_sync(0xffffffffu, s1, 2);
        if (tig == 0) { reds[r0 * 2 + wn] = s0; reds[(r0 + 8) * 2 + wn] = s1; }
        __syncthreads();
        const float inv0 = 1.0f / (reds[r0 * 2] + reds[r0 * 2 + 1]);
        const float inv1 = 1.0f / (reds[(r0 + 8) * 2] + reds[(r0 + 8) * 2 + 1]);

        // write plain fp16 P
#pragma unroll
        for (int nt = 0; nt < 16; nt++) {
            const int col = wn * 128 + nt * 8 + tig * 2;
            *(uint32_t*)(smc + PH_O + r0 * P_ROW_B + col * 2) =
                pack_h2(acc[nt][0] * inv0, acc[nt][1] * inv0);
            *(uint32_t*)(smc + PH_O + (r0 + 8) * P_ROW_B + col * 2) =
                pack_h2(acc[nt][2] * inv1, acc[nt][3] * inv1);
        }
    }
    __syncthreads();

    // ---------------- Phase 3: O = P V ----------------
    __half* Vh = (__half*)(smc + VH_O);
    const uint32_t vbo = smb + VH_O
        + (uint32_t)((wn * 128 + ((lane >> 4) << 3) + (lane & 7)) * 48
                     + ((lane >> 3) & 1) * 16);
    float* ob = o + (size_t)bl * C_ * D_ + (size_t)ct * 64 * D_;

    for (int h = 0; h < 2; h++) {
        float oacc[16][4];
#pragma unroll
        for (int nt = 0; nt < 16; nt++)
#pragma unroll
            for (int i = 0; i < 4; i++) oacc[nt][i] = 0.0f;

        for (int s0i = 0; s0i < S_; s0i += 16) {
            // stage V chunk transposed: Vh[d][s], plain fp16
#pragma unroll
            for (int i = 0; i < 4; i++) {
                const int e  = tid + i * 256;
                const int s  = e >> 6;            // 0..15
                const int d4 = (e & 63) * 4;      // 0..252
                float4 vv = *(const float4*)(Vb + (size_t)(s0i + s) * D_ + h * 256 + d4);
                Vh[(d4 + 0) * 24 + s] = __float2half_rn(vv.x);
                Vh[(d4 + 1) * 24 + s] = __float2half_rn(vv.y);
                Vh[(d4 + 2) * 24 + s] = __float2half_rn(vv.z);
                Vh[(d4 + 3) * 24 + s] = __float2half_rn(vv.w);
            }
            __syncthreads();

            uint32_t af[4];
            ldsm_x4(af, smb + PH_O + pa + (uint32_t)s0i * 2);
#pragma unroll
            for (int p = 0; p < 8; p++) {
                uint32_t bf[4];
                ldsm_x4(bf, vbo + (uint32_t)p * 768);
                mma_f16(oacc[2*p    ], af, &bf[0]);
                mma_f16(oacc[2*p + 1], af, &bf[2]);
            }
            __syncthreads();
        }

#pragma unroll
        for (int nt = 0; nt < 16; nt++) {
            const int col = h * 256 + wn * 128 + nt * 8 + tig * 2;
            const int r0  = wm * 16 + g;
            float2 v0, v1;
            v0.x = oacc[nt][0]; v0.y = oacc[nt][1];
            v1.x = oacc[nt][2]; v1.y = oacc[nt][3];
            *(float2*)(ob + (size_t)r0 * D_ + col)       = v0;
            *(float2*)(ob + (size_t)(r0 + 8) * D_ + col) = v1;
        }
    }
}

// ---------------------------------------------------------------------------
extern "C" void kernel_launch(void* const* d_in, const int* in_sizes, int n_in,
                              void* d_out, int out_size)
{
    (void)in_sizes; (void)n_in; (void)out_size;
    const float* queries = (const float*)d_in[0];
    const float* keys    = (const float*)d_in[1];
    const float* values  = (const float*)d_in[2];
    const float* Wq      = (const float*)d_in[3];
    const float* bq      = (const float*)d_in[4];
    const float* Wkv     = (const float*)d_in[5];
    const float* bkv     = (const float*)d_in[6];
    const float* Wo      = (const float*)d_in[7];
    const float* bo      = (const float*)d_in[8];
    float* out = (float*)d_out;

    float *p_q, *p_k, *p_v, *p_att;
    cudaGetSymbolAddress((void**)&p_q,   g_q);
    cudaGetSymbolAddress((void**)&p_k,   g_k);
    cudaGetSymbolAddress((void**)&p_v,   g_v);
    cudaGetSymbolAddress((void**)&p_att, g_att);

    (void)cudaFuncSetAttribute(attn_f16_kernel,
                               cudaFuncAttributeMaxDynamicSharedMemorySize,
                               ATTN_SMEM);

    dim3 gblk(256);
    dim3 ggrid(D_ / 128, NQ / 128);   // (4, 256)

    gemm_nt_f16<<<ggrid, gblk>>>(queries, Wq,  bq,  p_q, NQ, D_);
    gemm_nt_f16<<<ggrid, gblk>>>(keys,    Wkv, bkv, p_k, NQ, D_);
    gemm_nt_f16<<<ggrid, gblk>>>(values,  Wkv, bkv, p_v, NQ, D_);

    attn_f16_kernel<<<B_ * L_ * (C_ / 64), 256, ATTN_SMEM>>>(p_q, p_k, p_v, p_att);

    gemm_nt_f16<<<ggrid, gblk>>>(p_att, Wo, bo, out, NQ, D_);
}

// round 10
// speedup vs baseline: 7.4938x; 1.2235x over previous
#include <cuda_runtime.h>
#include <cuda_fp16.h>
#include <math.h>
#include <stdint.h>

#define B_ 2
#define L_ 64
#define C_ 256
#define S_ 256
#define D_ 512
#define NQ (B_*L_*C_)   /* 32768 rows */

// Scratch (module-load allocated; no runtime allocs) — fp16 pipeline
__device__ __half g_qh[(size_t)NQ * D_];
__device__ __half g_ql[(size_t)NQ * D_];
__device__ __half g_kh[(size_t)NQ * D_];
__device__ __half g_kl[(size_t)NQ * D_];
__device__ __half g_vh[(size_t)NQ * D_];
__device__ __half g_oh[(size_t)NQ * D_];
__device__ __half g_whq [(size_t)D_ * D_];
__device__ __half g_whkv[(size_t)D_ * D_];
__device__ __half g_who [(size_t)D_ * D_];

// ---------------------------------------------------------------------------
// helpers
// ---------------------------------------------------------------------------
__device__ __forceinline__ uint32_t smem_u32(const void* p) {
    uint32_t a;
    asm("{ .reg .u64 t; cvta.to.shared.u64 t, %1; cvt.u32.u64 %0, t; }"
        : "=r"(a) : "l"(p));
    return a;
}
__device__ __forceinline__ uint32_t pack_h2(float a, float b) {
    __half2 h = __floats2half2_rn(a, b);
    return *(uint32_t*)&h;
}
__device__ __forceinline__ void split2h(float a, float b, uint32_t& h, uint32_t& l) {
    __half ha = __float2half_rn(a);
    __half hb = __float2half_rn(b);
    __half la = __float2half_rn(a - __half2float(ha));
    __half lb = __float2half_rn(b - __half2float(hb));
    __half2 hp = __halves2half2(ha, hb);
    __half2 lp = __halves2half2(la, lb);
    h = *(uint32_t*)&hp;
    l = *(uint32_t*)&lp;
}
__device__ __forceinline__ void mma_f16(float d[4], const uint32_t a[4],
                                        const uint32_t b[2]) {
    asm volatile(
        "mma.sync.aligned.m16n8k16.row.col.f32.f16.f16.f32 "
        "{%0,%1,%2,%3}, {%4,%5,%6,%7}, {%8,%9}, {%0,%1,%2,%3};\n"
        : "+f"(d[0]), "+f"(d[1]), "+f"(d[2]), "+f"(d[3])
        : "r"(a[0]), "r"(a[1]), "r"(a[2]), "r"(a[3]),
          "r"(b[0]), "r"(b[1]));
}
__device__ __forceinline__ void ldsm_x4(uint32_t r[4], uint32_t addr) {
    asm volatile("ldmatrix.sync.aligned.m8n8.x4.shared.b16 {%0,%1,%2,%3}, [%4];"
        : "=r"(r[0]), "=r"(r[1]), "=r"(r[2]), "=r"(r[3]) : "r"(addr));
}
__device__ __forceinline__ void ldsm_x4_t(uint32_t r[4], uint32_t addr) {
    asm volatile("ldmatrix.sync.aligned.m8n8.x4.trans.shared.b16 {%0,%1,%2,%3}, [%4];"
        : "=r"(r[0]), "=r"(r[1]), "=r"(r[2]), "=r"(r[3]) : "r"(addr));
}

// ---------------------------------------------------------------------------
// Weight convert: fp32 [512x512] -> fp16
// ---------------------------------------------------------------------------
__global__ __launch_bounds__(256) void convert_w(const float* __restrict__ W,
                                                 __half* __restrict__ Wh)
{
    const int i = blockIdx.x * 256 + threadIdx.x;   // 0..32767, 8 elems each
    float4 a = ((const float4*)W)[i * 2];
    float4 b = ((const float4*)W)[i * 2 + 1];
    uint4 u;
    u.x = pack_h2(a.x, a.y); u.y = pack_h2(a.z, a.w);
    u.z = pack_h2(b.x, b.y); u.w = pack_h2(b.z, b.w);
    ((uint4*)Wh)[i] = u;
}

// ---------------------------------------------------------------------------
// Templated NT GEMM:  C = A[M,512] * Wh[N,512]^T + bias
//  AM: 0 = A fp32 (convert in staging), 1 = A fp16 (pure copy)
//  OM: 0 = fp32 out, 1 = fp16 plain out, 2 = fp16 hi/lo split out
// 128x128 tile, BK=16, 256 thr = 8 warps (4m x 2n), double-buffered, ldmatrix.
// ---------------------------------------------------------------------------
#define GK 512
#define GNIT (GK/16)

template<int AM, int OM>
__global__ __launch_bounds__(256) void gemm_f16(
    const void* __restrict__ Ain, const __half* __restrict__ Bh,
    const float* __restrict__ bias, void* __restrict__ Cout,
    void* __restrict__ Cout2)
{
    __shared__ __half As[2][128 * 24];
    __shared__ __half Bs[2][128 * 24];

    const int tid  = threadIdx.x;
    const int wid  = tid >> 5;
    const int lane = tid & 31;
    const int g    = lane >> 2;
    const int tig  = lane & 3;
    const int wm = wid & 3;
    const int wn = wid >> 2;
    const int row0 = blockIdx.y * 128;
    const int col0 = blockIdx.x * 128;
    const int N = D_;

    const int lrow = tid >> 1;          // 0..127
    const int ke   = (tid & 1) * 8;     // element offset 0/8

    const float*  A32 = (const float*)Ain;
    const __half* A16 = (const __half*)Ain;
    const float*  Ap32 = A32 + (size_t)(row0 + lrow) * GK + ke;
    const __half* Ap16 = A16 + (size_t)(row0 + lrow) * GK + ke;
    const __half* Bp   = Bh  + (size_t)(col0 + lrow) * GK + ke;

    const uint32_t asb = smem_u32(As[0]);
    const uint32_t bsb = smem_u32(Bs[0]);
    const uint32_t aoff = (uint32_t)((wm * 32 + (lane & 15)) * 48 + (lane >> 4) * 16);
    const uint32_t boff = (uint32_t)((wn * 64 + ((lane >> 4) << 3) + (lane & 7)) * 48
                                     + ((lane >> 3) & 1) * 16);

    float acc[2][8][4];
#pragma unroll
    for (int mt = 0; mt < 2; mt++)
#pragma unroll
        for (int nt = 0; nt < 8; nt++)
#pragma unroll
            for (int i = 0; i < 4; i++) acc[mt][nt][i] = 0.0f;

    float4 ra0, ra1;      // AM==0 regs
    uint4  ra;            // AM==1 regs
    uint4  rb;

    auto ldgA = [&](int it) {
        if constexpr (AM == 0) {
            ra0 = *(const float4*)(Ap32 + it * 16);
            ra1 = *(const float4*)(Ap32 + it * 16 + 4);
        } else {
            ra = *(const uint4*)(Ap16 + it * 16);
        }
        rb = *(const uint4*)(Bp + it * 16);
    };
    auto stsA = [&](int buf) {
        if constexpr (AM == 0) {
            uint4 u;
            u.x = pack_h2(ra0.x, ra0.y); u.y = pack_h2(ra0.z, ra0.w);
            u.z = pack_h2(ra1.x, ra1.y); u.w = pack_h2(ra1.z, ra1.w);
            *(uint4*)&As[buf][lrow * 24 + ke] = u;
        } else {
            *(uint4*)&As[buf][lrow * 24 + ke] = ra;
        }
        *(uint4*)&Bs[buf][lrow * 24 + ke] = rb;
    };

    ldgA(0); stsA(0); ldgA(1);
    __syncthreads();

#pragma unroll 2
    for (int it = 0; it < GNIT; it++) {
        const int cur = it & 1;
        if (it + 1 < GNIT) stsA(cur ^ 1);
        if (it + 2 < GNIT) ldgA(it + 2);

        const uint32_t ab = asb + (uint32_t)cur * (128 * 48) + aoff;
        const uint32_t bb = bsb + (uint32_t)cur * (128 * 48) + boff;
        uint32_t af[2][4];
        ldsm_x4(af[0], ab);
        ldsm_x4(af[1], ab + 768);
        uint32_t bf[4][4];
#pragma unroll
        for (int p = 0; p < 4; p++)
            ldsm_x4(bf[p], bb + (uint32_t)p * 768);
#pragma unroll
        for (int mt = 0; mt < 2; mt++)
#pragma unroll
            for (int p = 0; p < 4; p++) {
                mma_f16(acc[mt][2*p    ], af[mt], &bf[p][0]);
                mma_f16(acc[mt][2*p + 1], af[mt], &bf[p][2]);
            }
        __syncthreads();
    }

#pragma unroll
    for (int nt = 0; nt < 8; nt++) {
        const int col = col0 + wn * 64 + nt * 8 + tig * 2;
        const float bx = bias[col];
        const float by = bias[col + 1];
#pragma unroll
        for (int mt = 0; mt < 2; mt++) {
            const int r = row0 + wm * 32 + mt * 16 + g;
            const float v0x = acc[mt][nt][0] + bx, v0y = acc[mt][nt][1] + by;
            const float v1x = acc[mt][nt][2] + bx, v1y = acc[mt][nt][3] + by;
            if constexpr (OM == 0) {
                float2 a; a.x = v0x; a.y = v0y;
                float2 b; b.x = v1x; b.y = v1y;
                *(float2*)((float*)Cout + (size_t)r * N + col)       = a;
                *(float2*)((float*)Cout + (size_t)(r + 8) * N + col) = b;
            } else if constexpr (OM == 1) {
                *(uint32_t*)((__half*)Cout + (size_t)r * N + col)       = pack_h2(v0x, v0y);
                *(uint32_t*)((__half*)Cout + (size_t)(r + 8) * N + col) = pack_h2(v1x, v1y);
            } else {
                uint32_t h, l;
                split2h(v0x, v0y, h, l);
                *(uint32_t*)((__half*)Cout  + (size_t)r * N + col) = h;
                *(uint32_t*)((__half*)Cout2 + (size_t)r * N + col) = l;
                split2h(v1x, v1y, h, l);
                *(uint32_t*)((__half*)Cout  + (size_t)(r + 8) * N + col) = h;
                *(uint32_t*)((__half*)Cout2 + (size_t)(r + 8) * N + col) = l;
            }
        }
    }
}

// ---------------------------------------------------------------------------
// fp16 attention, register-pipelined staging.
//  P1: S = Q K^T, 3-term hi/lo fp16 (pre-split inputs), double-buffered smem
//  P2: register softmax
//  P3: O = P V, V staged row-major + ldmatrix.trans, double-buffered
// smem: P1 2x30720; P3: P[64x528B]=33792 | V 2x8448 | RED 1024 -> 61440 B
// ---------------------------------------------------------------------------
#define P1_BUF   30720
#define QH_O     0
#define QL_O     3072
#define KH_O     6144
#define KL_O     18432
#define PH_O     0
#define P_ROW_B  528
#define VH_O     33792
#define V_BUF    8448
#define V_ROW_B  528
#define RED_O    50688
#define ATTN_SMEM 61440

__global__ __launch_bounds__(256) void attn_f16_kernel(
    const __half* __restrict__ qh, const __half* __restrict__ ql,
    const __half* __restrict__ kh, const __half* __restrict__ kl,
    const __half* __restrict__ vh, __half* __restrict__ o)
{
    extern __shared__ char smc[];
    const int tid  = threadIdx.x;
    const int wid  = tid >> 5;
    const int lane = tid & 31;
    const int g    = lane >> 2;
    const int tig  = lane & 3;
    const int wm   = wid & 3;
    const int wn   = wid >> 2;

    const int bl = blockIdx.x >> 2;
    const int ct = blockIdx.x & 3;

    const size_t qoff = (size_t)(bl * C_ + ct * 64) * D_;
    const size_t koff = (size_t)bl * S_ * D_;
    const __half* Vb = vh + koff;

    const uint32_t smb = smem_u32(smc);
    const uint32_t qa  = (uint32_t)((wm * 16 + (lane & 15)) * 48 + (lane >> 4) * 16);
    const uint32_t kb_ = (uint32_t)((wn * 128 + ((lane >> 4) << 3) + (lane & 7)) * 48
                                    + ((lane >> 3) & 1) * 16);
    const uint32_t pa  = (uint32_t)((wm * 16 + (lane & 15)) * P_ROW_B + (lane >> 4) * 16);
    const uint32_t va  = (uint32_t)(((((lane >> 3) & 1) * 8 + (lane & 7)) * V_ROW_B)
                                    + (lane >> 4) * 16 + wn * 256);

    float acc[16][4];
#pragma unroll
    for (int nt = 0; nt < 16; nt++)
#pragma unroll
        for (int i = 0; i < 4; i++) acc[nt][i] = 0.0f;

    const int qrow = tid >> 2;          // 0..63
    const int kc   = (tid & 3) * 4;     // halves 0,4,8,12

    // ---------------- Phase 1 ----------------
    uint2 rqh, rql, rkh[4], rkl[4];
    auto ldg1 = [&](int it) {
        const int k0 = it * 16 + kc;
        rqh = *(const uint2*)(qh + qoff + (size_t)qrow * D_ + k0);
        rql = *(const uint2*)(ql + qoff + (size_t)qrow * D_ + k0);
#pragma unroll
        for (int i = 0; i < 4; i++) {
            const size_t r = koff + (size_t)(qrow + i * 64) * D_ + k0;
            rkh[i] = *(const uint2*)(kh + r);
            rkl[i] = *(const uint2*)(kl + r);
        }
    };
    auto sts1 = [&](int b) {
        char* base = smc + b * P1_BUF;
        *(uint2*)(base + QH_O + qrow * 48 + kc * 2) = rqh;
        *(uint2*)(base + QL_O + qrow * 48 + kc * 2) = rql;
#pragma unroll
        for (int i = 0; i < 4; i++) {
            *(uint2*)(base + KH_O + (qrow + i * 64) * 48 + kc * 2) = rkh[i];
            *(uint2*)(base + KL_O + (qrow + i * 64) * 48 + kc * 2) = rkl[i];
        }
    };

    ldg1(0); sts1(0); ldg1(1);
    __syncthreads();

    for (int it = 0; it < D_ / 16; it++) {
        const int cur = it & 1;
        if (it + 1 < D_ / 16) sts1(cur ^ 1);
        if (it + 2 < D_ / 16) ldg1(it + 2);

        const uint32_t bufb = smb + (uint32_t)cur * P1_BUF;
        uint32_t ah[4], al[4];
        ldsm_x4(ah, bufb + QH_O + qa);
        ldsm_x4(al, bufb + QL_O + qa);
#pragma unroll
        for (int p = 0; p < 8; p++) {
            uint32_t bh[4], blo[4];
            ldsm_x4(bh,  bufb + KH_O + kb_ + (uint32_t)p * 768);
            ldsm_x4(blo, bufb + KL_O + kb_ + (uint32_t)p * 768);
            mma_f16(acc[2*p    ], ah, &blo[0]);
            mma_f16(acc[2*p    ], al, &bh[0]);
            mma_f16(acc[2*p    ], ah, &bh[0]);
            mma_f16(acc[2*p + 1], ah, &blo[2]);
            mma_f16(acc[2*p + 1], al, &bh[2]);
            mma_f16(acc[2*p + 1], ah, &bh[2]);
        }
        __syncthreads();
    }

    // ---------------- Phase 2: register softmax ----------------
    {
        float* redm = (float*)(smc + RED_O);
        float* reds = redm + 128;
        const float scale = 0.04419417382415922f;
        const int r0 = wm * 16 + g;

        float mx0 = -1e30f, mx1 = -1e30f;
#pragma unroll
        for (int nt = 0; nt < 16; nt++) {
            acc[nt][0] *= scale; acc[nt][1] *= scale;
            acc[nt][2] *= scale; acc[nt][3] *= scale;
            mx0 = fmaxf(mx0, fmaxf(acc[nt][0], acc[nt][1]));
            mx1 = fmaxf(mx1, fmaxf(acc[nt][2], acc[nt][3]));
        }
        mx0 = fmaxf(mx0, __shfl_xor_sync(0xffffffffu, mx0, 1));
        mx0 = fmaxf(mx0, __shfl_xor_sync(0xffffffffu, mx0, 2));
        mx1 = fmaxf(mx1, __shfl_xor_sync(0xffffffffu, mx1, 1));
        mx1 = fmaxf(mx1, __shfl_xor_sync(0xffffffffu, mx1, 2));
        if (tig == 0) { redm[r0 * 2 + wn] = mx0; redm[(r0 + 8) * 2 + wn] = mx1; }
        __syncthreads();
        const float m0 = fmaxf(redm[r0 * 2], redm[r0 * 2 + 1]);
        const float m1 = fmaxf(redm[(r0 + 8) * 2], redm[(r0 + 8) * 2 + 1]);

        float s0 = 0.0f, s1 = 0.0f;
#pragma unroll
        for (int nt = 0; nt < 16; nt++) {
            acc[nt][0] = __expf(acc[nt][0] - m0); s0 += acc[nt][0];
            acc[nt][1] = __expf(acc[nt][1] - m0); s0 += acc[nt][1];
            acc[nt][2] = __expf(acc[nt][2] - m1); s1 += acc[nt][2];
            acc[nt][3] = __expf(acc[nt][3] - m1); s1 += acc[nt][3];
        }
        s0 += __shfl_xor_sync(0xffffffffu, s0, 1);
        s0 += __shfl_xor_sync(0xffffffffu, s0, 2);
        s1 += __shfl_xor_sync(0xffffffffu, s1, 1);
        s1 += __shfl_xor_sync(0xffffffffu, s1, 2);
        if (tig == 0) { reds[r0 * 2 + wn] = s0; reds[(r0 + 8) * 2 + wn] = s1; }
        __syncthreads();
        const float inv0 = 1.0f / (reds[r0 * 2] + reds[r0 * 2 + 1]);
        const float inv1 = 1.0f / (reds[(r0 + 8) * 2] + reds[(r0 + 8) * 2 + 1]);

#pragma unroll
        for (int nt = 0; nt < 16; nt++) {
            const int col = wn * 128 + nt * 8 + tig * 2;
            *(uint32_t*)(smc + PH_O + r0 * P_ROW_B + col * 2) =
                pack_h2(acc[nt][0] * inv0, acc[nt][1] * inv0);
            *(uint32_t*)(smc + PH_O + (r0 + 8) * P_ROW_B + col * 2) =
                pack_h2(acc[nt][2] * inv1, acc[nt][3] * inv1);
        }
    }
    __syncthreads();

    // ---------------- Phase 3: O = P V ----------------
    const int vrow = tid >> 5;          // 0..7 (x2 via +8)
    const int vc16 = (tid & 31);        // 16B column group within 512B
    __half* ob = o + qoff;

    uint4 rv0, rv1;
    auto ldgv = [&](int ci) {
        const int s0 = (ci & 15) * 16;
        const int hh = ci >> 4;
        rv0 = *(const uint4*)(Vb + (size_t)(s0 + vrow) * D_ + hh * 256 + vc16 * 8);
        rv1 = *(const uint4*)(Vb + (size_t)(s0 + vrow + 8) * D_ + hh * 256 + vc16 * 8);
    };
    auto stsv = [&](int b) {
        char* base = smc + VH_O + b * V_BUF;
        *(uint4*)(base + vrow * V_ROW_B + vc16 * 16) = rv0;
        *(uint4*)(base + (vrow + 8) * V_ROW_B + vc16 * 16) = rv1;
    };

    for (int h = 0; h < 2; h++) {
        float oacc[16][4];
#pragma unroll
        for (int nt = 0; nt < 16; nt++)
#pragma unroll
            for (int i = 0; i < 4; i++) oacc[nt][i] = 0.0f;

        ldgv(h * 16); stsv(0); ldgv(h * 16 + 1);
        __syncthreads();

        for (int j = 0; j < 16; j++) {
            const int cur = j & 1;
            if (j + 1 < 16) stsv(cur ^ 1);
            if (j + 2 < 16) ldgv(h * 16 + j + 2);

            uint32_t af[4];
            ldsm_x4(af, smb + PH_O + pa + (uint32_t)j * 32);
            const uint32_t vb_ = smb + VH_O + (uint32_t)cur * V_BUF + va;
#pragma unroll
            for (int p = 0; p < 8; p++) {
                uint32_t bf[4];
                ldsm_x4_t(bf, vb_ + (uint32_t)p * 32);
                mma_f16(oacc[2*p    ], af, &bf[0]);
                mma_f16(oacc[2*p + 1], af, &bf[2]);
            }
            __syncthreads();
        }

#pragma unroll
        for (int nt = 0; nt < 16; nt++) {
            const int col = h * 256 + wn * 128 + nt * 8 + tig * 2;
            const int r0  = wm * 16 + g;
            *(uint32_t*)(ob + (size_t)r0 * D_ + col) =
                pack_h2(oacc[nt][0], oacc[nt][1]);
            *(uint32_t*)(ob + (size_t)(r0 + 8) * D_ + col) =
                pack_h2(oacc[nt][2], oacc[nt][3]);
        }
    }
}

// ---------------------------------------------------------------------------
extern "C" void kernel_launch(void* const* d_in, const int* in_sizes, int n_in,
                              void* d_out, int out_size)
{
    (void)in_sizes; (void)n_in; (void)out_size;
    const float* queries = (const float*)d_in[0];
    const float* keys    = (const float*)d_in[1];
    const float* values  = (const float*)d_in[2];
    const float* Wq      = (const float*)d_in[3];
    const float* bq      = (const float*)d_in[4];
    const float* Wkv     = (const float*)d_in[5];
    const float* bkv     = (const float*)d_in[6];
    const float* Wo      = (const float*)d_in[7];
    const float* bo      = (const float*)d_in[8];
    float* out = (float*)d_out;

    __half *qh, *ql, *kh, *kl, *vh, *oh, *whq, *whkv, *who;
    cudaGetSymbolAddress((void**)&qh,   g_qh);
    cudaGetSymbolAddress((void**)&ql,   g_ql);
    cudaGetSymbolAddress((void**)&kh,   g_kh);
    cudaGetSymbolAddress((void**)&kl,   g_kl);
    cudaGetSymbolAddress((void**)&vh,   g_vh);
    cudaGetSymbolAddress((void**)&oh,   g_oh);
    cudaGetSymbolAddress((void**)&whq,  g_whq);
    cudaGetSymbolAddress((void**)&whkv, g_whkv);
    cudaGetSymbolAddress((void**)&who,  g_who);

    (void)cudaFuncSetAttribute(attn_f16_kernel,
                               cudaFuncAttributeMaxDynamicSharedMemorySize,
                               ATTN_SMEM);

    // Weights -> fp16 (once per launch)
    convert_w<<<128, 256>>>(Wq,  whq);
    convert_w<<<128, 256>>>(Wkv, whkv);
    convert_w<<<128, 256>>>(Wo,  who);

    dim3 gblk(256);
    dim3 ggrid(D_ / 128, NQ / 128);   // (4, 256)

    // Projections: q,k -> split fp16; v -> plain fp16
    gemm_f16<0, 2><<<ggrid, gblk>>>(queries, whq,  bq,  qh, ql);
    gemm_f16<0, 2><<<ggrid, gblk>>>(keys,    whkv, bkv, kh, kl);
    gemm_f16<0, 1><<<ggrid, gblk>>>(values,  whkv, bkv, vh, nullptr);

    // Attention (fp16-native)
    attn_f16_kernel<<<B_ * L_ * (C_ / 64), 256, ATTN_SMEM>>>(qh, ql, kh, kl, vh, oh);

    // Output projection: fp16 A -> fp32 out
    gemm_f16<1, 0><<<ggrid, gblk>>>(oh, who, bo, out, nullptr);
}

// round 12
// speedup vs baseline: 8.0606x; 1.0756x over previous
#include <cuda_runtime.h>
#include <cuda_fp16.h>
#include <math.h>
#include <stdint.h>

#define B_ 2
#define L_ 64
#define C_ 256
#define S_ 256
#define D_ 512
#define NQ (B_*L_*C_)   /* 32768 rows */

// Scratch (module-load allocated; no runtime allocs) — fp16 pipeline
__device__ __half g_qh[(size_t)NQ * D_];
__device__ __half g_ql[(size_t)NQ * D_];
__device__ __half g_kh[(size_t)NQ * D_];
__device__ __half g_kl[(size_t)NQ * D_];
__device__ __half g_vh[(size_t)NQ * D_];
__device__ __half g_oh[(size_t)NQ * D_];
__device__ __half g_whq [(size_t)D_ * D_];
__device__ __half g_whkv[(size_t)D_ * D_];
__device__ __half g_who [(size_t)D_ * D_];

// ---------------------------------------------------------------------------
// helpers
// ---------------------------------------------------------------------------
__device__ __forceinline__ uint32_t smem_u32(const void* p) {
    uint32_t a;
    asm("{ .reg .u64 t; cvta.to.shared.u64 t, %1; cvt.u32.u64 %0, t; }"
        : "=r"(a) : "l"(p));
    return a;
}
__device__ __forceinline__ uint32_t pack_h2(float a, float b) {
    __half2 h = __floats2half2_rn(a, b);
    return *(uint32_t*)&h;
}
__device__ __forceinline__ void split2h(float a, float b, uint32_t& h, uint32_t& l) {
    __half ha = __float2half_rn(a);
    __half hb = __float2half_rn(b);
    __half la = __float2half_rn(a - __half2float(ha));
    __half lb = __float2half_rn(b - __half2float(hb));
    __half2 hp = __halves2half2(ha, hb);
    __half2 lp = __halves2half2(la, lb);
    h = *(uint32_t*)&hp;
    l = *(uint32_t*)&lp;
}
__device__ __forceinline__ void mma_f16(float d[4], const uint32_t a[4],
                                        const uint32_t b[2]) {
    asm volatile(
        "mma.sync.aligned.m16n8k16.row.col.f32.f16.f16.f32 "
        "{%0,%1,%2,%3}, {%4,%5,%6,%7}, {%8,%9}, {%0,%1,%2,%3};\n"
        : "+f"(d[0]), "+f"(d[1]), "+f"(d[2]), "+f"(d[3])
        : "r"(a[0]), "r"(a[1]), "r"(a[2]), "r"(a[3]),
          "r"(b[0]), "r"(b[1]));
}
__device__ __forceinline__ void ldsm_x4(uint32_t r[4], uint32_t addr) {
    asm volatile("ldmatrix.sync.aligned.m8n8.x4.shared.b16 {%0,%1,%2,%3}, [%4];"
        : "=r"(r[0]), "=r"(r[1]), "=r"(r[2]), "=r"(r[3]) : "r"(addr));
}
__device__ __forceinline__ void ldsm_x4_t(uint32_t r[4], uint32_t addr) {
    asm volatile("ldmatrix.sync.aligned.m8n8.x4.trans.shared.b16 {%0,%1,%2,%3}, [%4];"
        : "=r"(r[0]), "=r"(r[1]), "=r"(r[2]), "=r"(r[3]) : "r"(addr));
}
__device__ __forceinline__ void cp16(uint32_t smem_dst, const void* gptr) {
    asm volatile("cp.async.ca.shared.global [%0], [%1], 16;"
                 :: "r"(smem_dst), "l"(gptr));
}
#define CP_COMMIT() asm volatile("cp.async.commit_group;" ::: "memory")
#define CP_WAIT0()  asm volatile("cp.async.wait_group 0;" ::: "memory")

// ---------------------------------------------------------------------------
// Weight convert: 3x fp32 [512x512] -> fp16 in one launch
// ---------------------------------------------------------------------------
__global__ __launch_bounds__(256) void convert_w3(
    const float* __restrict__ W0, __half* __restrict__ H0,
    const float* __restrict__ W1, __half* __restrict__ H1,
    const float* __restrict__ W2, __half* __restrict__ H2)
{
    const int b = blockIdx.x;                 // 0..383
    const int w = b >> 7;                     // which weight
    const float* W = w == 0 ? W0 : (w == 1 ? W1 : W2);
    __half* H = w == 0 ? H0 : (w == 1 ? H1 : H2);
    const int i = (b & 127) * 256 + threadIdx.x;   // 0..32767, 8 elems each
    float4 a = ((const float4*)W)[i * 2];
    float4 c = ((const float4*)W)[i * 2 + 1];
    uint4 u;
    u.x = pack_h2(a.x, a.y); u.y = pack_h2(a.z, a.w);
    u.z = pack_h2(c.x, c.y); u.w = pack_h2(c.z, c.w);
    ((uint4*)H)[i] = u;
}

// ---------------------------------------------------------------------------
// Fused q/k/v projection GEMM: BK=32, cp.async weights, register-staged A.
//   blockIdx.z: 0 -> q (split out), 1 -> k (split out), 2 -> v (plain out)
// 128x128 tile, 256 thr = 8 warps (4m x 2n), smem rows 32->40 halves (80B).
// ---------------------------------------------------------------------------
#define GK 512
#define BK32 32
#define NIT (GK/BK32)        /* 16 */
#define ROWB 80              /* bytes per smem row */
#define BUFB32 (128*ROWB)    /* 10240 */

__global__ __launch_bounds__(256) void gemm_qkv(
    const float* __restrict__ qin, const float* __restrict__ kin,
    const float* __restrict__ vin,
    const __half* __restrict__ whq, const __half* __restrict__ whkv,
    const float* __restrict__ bq, const float* __restrict__ bkv,
    __half* __restrict__ qh, __half* __restrict__ ql,
    __half* __restrict__ kh, __half* __restrict__ kl,
    __half* __restrict__ vh)
{
    __shared__ __half As[2][128 * 40];
    __shared__ __half Bs[2][128 * 40];

    const int z = blockIdx.z;
    const float*  A    = z == 0 ? qin : (z == 1 ? kin : vin);
    const __half* W    = z == 0 ? whq : whkv;
    const float*  bias = z == 0 ? bq  : bkv;

    const int tid  = threadIdx.x;
    const int wid  = tid >> 5;
    const int lane = tid & 31;
    const int g    = lane >> 2;
    const int tig  = lane & 3;
    const int wm = wid & 3;
    const int wn = wid >> 2;
    const int row0 = blockIdx.y * 128;
    const int col0 = blockIdx.x * 128;

    const int lrow = tid >> 1;          // 0..127
    const int ke   = (tid & 1) * 16;    // half-element offset 0/16

    const float*  Ap = A + (size_t)(row0 + lrow) * GK + ke;
    const __half* Bp = W + (size_t)(col0 + lrow) * GK + ke;

    const uint32_t asb = smem_u32(As[0]);
    const uint32_t bsb = smem_u32(Bs[0]);
    const uint32_t sts_a = asb + (uint32_t)(lrow * ROWB + ke * 2);
    const uint32_t sts_b = bsb + (uint32_t)(lrow * ROWB + ke * 2);
    const uint32_t aoff = (uint32_t)((wm * 32 + (lane & 15)) * ROWB + (lane >> 4) * 16);
    const uint32_t boff = (uint32_t)((wn * 64 + ((lane >> 4) << 3) + (lane & 7)) * ROWB
                                     + ((lane >> 3) & 1) * 16);

    float acc[2][8][4];
#pragma unroll
    for (int mt = 0; mt < 2; mt++)
#pragma unroll
        for (int nt = 0; nt < 8; nt++)
#pragma unroll
            for (int i = 0; i < 4; i++) acc[mt][nt][i] = 0.0f;

    float4 raf[4];
    auto ldgA = [&](int it) {
        const float* p = Ap + it * BK32;
        raf[0] = *(const float4*)(p + 0);
        raf[1] = *(const float4*)(p + 4);
        raf[2] = *(const float4*)(p + 8);
        raf[3] = *(const float4*)(p + 12);
    };
    auto stsA = [&](int buf) {
        uint4 u0, u1;
        u0.x = pack_h2(raf[0].x, raf[0].y); u0.y = pack_h2(raf[0].z, raf[0].w);
        u0.z = pack_h2(raf[1].x, raf[1].y); u0.w = pack_h2(raf[1].z, raf[1].w);
        u1.x = pack_h2(raf[2].x, raf[2].y); u1.y = pack_h2(raf[2].z, raf[2].w);
        u1.z = pack_h2(raf[3].x, raf[3].y); u1.w = pack_h2(raf[3].z, raf[3].w);
        *(uint4*)((char*)As[buf] + lrow * ROWB + ke * 2)      = u0;
        *(uint4*)((char*)As[buf] + lrow * ROWB + ke * 2 + 16) = u1;
    };
    auto cpaB = [&](int it, int buf) {
        const uint32_t d = sts_b + (uint32_t)buf * BUFB32;
        const __half* s = Bp + it * BK32;
        cp16(d, s);
        cp16(d + 16, s + 8);
    };

    // prologue
    cpaB(0, 0); CP_COMMIT();
    ldgA(0); stsA(0);
    cpaB(1, 1); CP_COMMIT();
    ldgA(1);
    CP_WAIT0();
    __syncthreads();

    for (int it = 0; it < NIT; it++) {
        const int cur = it & 1;
        if (it + 1 < NIT) stsA(cur ^ 1);
        if (it + 2 < NIT) ldgA(it + 2);

        const uint32_t ab = asb + (uint32_t)cur * BUFB32 + aoff;
        const uint32_t bb = bsb + (uint32_t)cur * BUFB32 + boff;
#pragma unroll
        for (int kg = 0; kg < 2; kg++) {
            uint32_t af[2][4];
            ldsm_x4(af[0], ab + kg * 32);
            ldsm_x4(af[1], ab + kg * 32 + 16 * ROWB);
#pragma unroll
            for (int p = 0; p < 4; p++) {
                uint32_t bf[4];
                ldsm_x4(bf, bb + (uint32_t)p * (16 * ROWB) + kg * 32);
                mma_f16(acc[0][2*p    ], af[0], &bf[0]);
                mma_f16(acc[0][2*p + 1], af[0], &bf[2]);
                mma_f16(acc[1][2*p    ], af[1], &bf[0]);
                mma_f16(acc[1][2*p + 1], af[1], &bf[2]);
            }
        }
        if (it + 1 < NIT) CP_WAIT0();
        __syncthreads();
        if (it + 2 < NIT) { cpaB(it + 2, cur); CP_COMMIT(); }
    }

    // epilogue
#pragma unroll
    for (int nt = 0; nt < 8; nt++) {
        const int col = col0 + wn * 64 + nt * 8 + tig * 2;
        const float bx = bias[col];
        const float by = bias[col + 1];
#pragma unroll
        for (int mt = 0; mt < 2; mt++) {
            const int r = row0 + wm * 32 + mt * 16 + g;
            const float v0x = acc[mt][nt][0] + bx, v0y = acc[mt][nt][1] + by;
            const float v1x = acc[mt][nt][2] + bx, v1y = acc[mt][nt][3] + by;
            if (z == 2) {
                *(uint32_t*)(vh + (size_t)r * D_ + col)       = pack_h2(v0x, v0y);
                *(uint32_t*)(vh + (size_t)(r + 8) * D_ + col) = pack_h2(v1x, v1y);
            } else {
                __half* Ch = z == 0 ? qh : kh;
                __half* Cl = z == 0 ? ql : kl;
                uint32_t h, l;
                split2h(v0x, v0y, h, l);
                *(uint32_t*)(Ch + (size_t)r * D_ + col) = h;
                *(uint32_t*)(Cl + (size_t)r * D_ + col) = l;
                split2h(v1x, v1y, h, l);
                *(uint32_t*)(Ch + (size_t)(r + 8) * D_ + col) = h;
                *(uint32_t*)(Cl + (size_t)(r + 8) * D_ + col) = l;
            }
        }
    }
}

// ---------------------------------------------------------------------------
// Final projection: A fp16 (attention out), cp.async both operands, fp32 out.
// ---------------------------------------------------------------------------
__global__ __launch_bounds__(256) void gemm_o(
    const __half* __restrict__ A, const __half* __restrict__ W,
    const float* __restrict__ bias, float* __restrict__ C)
{
    __shared__ __half As[2][128 * 40];
    __shared__ __half Bs[2][128 * 40];

    const int tid  = threadIdx.x;
    const int wid  = tid >> 5;
    const int lane = tid & 31;
    const int g    = lane >> 2;
    const int tig  = lane & 3;
    const int wm = wid & 3;
    const int wn = wid >> 2;
    const int row0 = blockIdx.y * 128;
    const int col0 = blockIdx.x * 128;
    const int N = D_;

    const int lrow = tid >> 1;
    const int ke   = (tid & 1) * 16;

    const __half* Ap = A + (size_t)(row0 + lrow) * GK + ke;
    const __half* Bp = W + (size_t)(col0 + lrow) * GK + ke;

    const uint32_t asb = smem_u32(As[0]);
    const uint32_t bsb = smem_u32(Bs[0]);
    const uint32_t sts_a = asb + (uint32_t)(lrow * ROWB + ke * 2);
    const uint32_t sts_b = bsb + (uint32_t)(lrow * ROWB + ke * 2);
    const uint32_t aoff = (uint32_t)((wm * 32 + (lane & 15)) * ROWB + (lane >> 4) * 16);
    const uint32_t boff = (uint32_t)((wn * 64 + ((lane >> 4) << 3) + (lane & 7)) * ROWB
                                     + ((lane >> 3) & 1) * 16);

    float acc[2][8][4];
#pragma unroll
    for (int mt = 0; mt < 2; mt++)
#pragma unroll
        for (int nt = 0; nt < 8; nt++)
#pragma unroll
            for (int i = 0; i < 4; i++) acc[mt][nt][i] = 0.0f;

    auto cpa = [&](int it, int buf) {
        const uint32_t da = sts_a + (uint32_t)buf * BUFB32;
        const uint32_t db = sts_b + (uint32_t)buf * BUFB32;
        const __half* sa = Ap + it * BK32;
        const __half* sb = Bp + it * BK32;
        cp16(da, sa); cp16(da + 16, sa + 8);
        cp16(db, sb); cp16(db + 16, sb + 8);
    };

    cpa(0, 0); CP_COMMIT();
    cpa(1, 1); CP_COMMIT();
    CP_WAIT0();
    __syncthreads();

    for (int it = 0; it < NIT; it++) {
        const int cur = it & 1;
        const uint32_t ab = asb + (uint32_t)cur * BUFB32 + aoff;
        const uint32_t bb = bsb + (uint32_t)cur * BUFB32 + boff;
#pragma unroll
        for (int kg = 0; kg < 2; kg++) {
            uint32_t af[2][4];
            ldsm_x4(af[0], ab + kg * 32);
            ldsm_x4(af[1], ab + kg * 32 + 16 * ROWB);
#pragma unroll
            for (int p = 0; p < 4; p++) {
                uint32_t bf[4];
                ldsm_x4(bf, bb + (uint32_t)p * (16 * ROWB) + kg * 32);
                mma_f16(acc[0][2*p    ], af[0], &bf[0]);
                mma_f16(acc[0][2*p + 1], af[0], &bf[2]);
                mma_f16(acc[1][2*p    ], af[1], &bf[0]);
                mma_f16(acc[1][2*p + 1], af[1], &bf[2]);
            }
        }
        if (it + 1 < NIT) CP_WAIT0();
        __syncthreads();
        if (it + 2 < NIT) { cpa(it + 2, cur); CP_COMMIT(); }
    }

#pragma unroll
    for (int nt = 0; nt < 8; nt++) {
        const int col = col0 + wn * 64 + nt * 8 + tig * 2;
        const float bx = bias[col];
        const float by = bias[col + 1];
#pragma unroll
        for (int mt = 0; mt < 2; mt++) {
            const int r = row0 + wm * 32 + mt * 16 + g;
            float2 a; a.x = acc[mt][nt][0] + bx; a.y = acc[mt][nt][1] + by;
            float2 b; b.x = acc[mt][nt][2] + bx; b.y = acc[mt][nt][3] + by;
            *(float2*)(C + (size_t)r * N + col)       = a;
            *(float2*)(C + (size_t)(r + 8) * N + col) = b;
        }
    }
}

// ---------------------------------------------------------------------------
// fp16 attention (unchanged from passing R10 kernel)
// ---------------------------------------------------------------------------
#define P1_BUF   30720
#define QH_O     0
#define QL_O     3072
#define KH_O     6144
#define KL_O     18432
#define PH_O     0
#define P_ROW_B  528
#define VH_O     33792
#define V_BUF    8448
#define V_ROW_B  528
#define RED_O    50688
#define ATTN_SMEM 61440

__global__ __launch_bounds__(256) void attn_f16_kernel(
    const __half* __restrict__ qh, const __half* __restrict__ ql,
    const __half* __restrict__ kh, const __half* __restrict__ kl,
    const __half* __restrict__ vh, __half* __restrict__ o)
{
    extern __shared__ char smc[];
    const int tid  = threadIdx.x;
    const int wid  = tid >> 5;
    const int lane = tid & 31;
    const int g    = lane >> 2;
    const int tig  = lane & 3;
    const int wm   = wid & 3;
    const int wn   = wid >> 2;

    const int bl = blockIdx.x >> 2;
    const int ct = blockIdx.x & 3;

    const size_t qoff = (size_t)(bl * C_ + ct * 64) * D_;
    const size_t koff = (size_t)bl * S_ * D_;
    const __half* Vb = vh + koff;

    const uint32_t smb = smem_u32(smc);
    const uint32_t qa  = (uint32_t)((wm * 16 + (lane & 15)) * 48 + (lane >> 4) * 16);
    const uint32_t kb_ = (uint32_t)((wn * 128 + ((lane >> 4) << 3) + (lane & 7)) * 48
                                    + ((lane >> 3) & 1) * 16);
    const uint32_t pa  = (uint32_t)((wm * 16 + (lane & 15)) * P_ROW_B + (lane >> 4) * 16);
    const uint32_t va  = (uint32_t)(((((lane >> 3) & 1) * 8 + (lane & 7)) * V_ROW_B)
                                    + (lane >> 4) * 16 + wn * 256);

    float acc[16][4];
#pragma unroll
    for (int nt = 0; nt < 16; nt++)
#pragma unroll
        for (int i = 0; i < 4; i++) acc[nt][i] = 0.0f;

    const int qrow = tid >> 2;
    const int kc   = (tid & 3) * 4;

    uint2 rqh, rql, rkh[4], rkl[4];
    auto ldg1 = [&](int it) {
        const int k0 = it * 16 + kc;
        rqh = *(const uint2*)(qh + qoff + (size_t)qrow * D_ + k0);
        rql = *(const uint2*)(ql + qoff + (size_t)qrow * D_ + k0);
#pragma unroll
        for (int i = 0; i < 4; i++) {
            const size_t r = koff + (size_t)(qrow + i * 64) * D_ + k0;
            rkh[i] = *(const uint2*)(kh + r);
            rkl[i] = *(const uint2*)(kl + r);
        }
    };
    auto sts1 = [&](int b) {
        char* base = smc + b * P1_BUF;
        *(uint2*)(base + QH_O + qrow * 48 + kc * 2) = rqh;
        *(uint2*)(base + QL_O + qrow * 48 + kc * 2) = rql;
#pragma unroll
        for (int i = 0; i < 4; i++) {
            *(uint2*)(base + KH_O + (qrow + i * 64) * 48 + kc * 2) = rkh[i];
            *(uint2*)(base + KL_O + (qrow + i * 64) * 48 + kc * 2) = rkl[i];
        }
    };

    ldg1(0); sts1(0); ldg1(1);
    __syncthreads();

    for (int it = 0; it < D_ / 16; it++) {
        const int cur = it & 1;
        if (it + 1 < D_ / 16) sts1(cur ^ 1);
        if (it + 2 < D_ / 16) ldg1(it + 2);

        const uint32_t bufb = smb + (uint32_t)cur * P1_BUF;
        uint32_t ah[4], al[4];
        ldsm_x4(ah, bufb + QH_O + qa);
        ldsm_x4(al, bufb + QL_O + qa);
#pragma unroll
        for (int p = 0; p < 8; p++) {
            uint32_t bh[4], blo[4];
            ldsm_x4(bh,  bufb + KH_O + kb_ + (uint32_t)p * 768);
            ldsm_x4(blo, bufb + KL_O + kb_ + (uint32_t)p * 768);
            mma_f16(acc[2*p    ], ah, &blo[0]);
            mma_f16(acc[2*p    ], al, &bh[0]);
            mma_f16(acc[2*p    ], ah, &bh[0]);
            mma_f16(acc[2*p + 1], ah, &blo[2]);
            mma_f16(acc[2*p + 1], al, &bh[2]);
            mma_f16(acc[2*p + 1], ah, &bh[2]);
        }
        __syncthreads();
    }

    {
        float* redm = (float*)(smc + RED_O);
        float* reds = redm + 128;
        const float scale = 0.04419417382415922f;
        const int r0 = wm * 16 + g;

        float mx0 = -1e30f, mx1 = -1e30f;
#pragma unroll
        for (int nt = 0; nt < 16; nt++) {
            acc[nt][0] *= scale; acc[nt][1] *= scale;
            acc[nt][2] *= scale; acc[nt][3] *= scale;
            mx0 = fmaxf(mx0, fmaxf(acc[nt][0], acc[nt][1]));
            mx1 = fmaxf(mx1, fmaxf(acc[nt][2], acc[nt][3]));
        }
        mx0 = fmaxf(mx0, __shfl_xor_sync(0xffffffffu, mx0, 1));
        mx0 = fmaxf(mx0, __shfl_xor_sync(0xffffffffu, mx0, 2));
        mx1 = fmaxf(mx1, __shfl_xor_sync(0xffffffffu, mx1, 1));
        mx1 = fmaxf(mx1, __shfl_xor_sync(0xffffffffu, mx1, 2));
        if (tig == 0) { redm[r0 * 2 + wn] = mx0; redm[(r0 + 8) * 2 + wn] = mx1; }
        __syncthreads();
        const float m0 = fmaxf(redm[r0 * 2], redm[r0 * 2 + 1]);
        const float m1 = fmaxf(redm[(r0 + 8) * 2], redm[(r0 + 8) * 2 + 1]);

        float s0 = 0.0f, s1 = 0.0f;
#pragma unroll
        for (int nt = 0; nt < 16; nt++) {
            acc[nt][0] = __expf(acc[nt][0] - m0); s0 += acc[nt][0];
            acc[nt][1] = __expf(acc[nt][1] - m0); s0 += acc[nt][1];
            acc[nt][2] = __expf(acc[nt][2] - m1); s1 += acc[nt][2];
            acc[nt][3] = __expf(acc[nt][3] - m1); s1 += acc[nt][3];
        }
        s0 += __shfl_xor_sync(0xffffffffu, s0, 1);
        s0 += __shfl_xor_sync(0xffffffffu, s0, 2);
        s1 += __shfl_xor_sync(0xffffffffu, s1, 1);
        s1 += __shfl_xor_sync(0xffffffffu, s1, 2);
        if (tig == 0) { reds[r0 * 2 + wn] = s0; reds[(r0 + 8) * 2 + wn] = s1; }
        __syncthreads();
        const float inv0 = 1.0f / (reds[r0 * 2] + reds[r0 * 2 + 1]);
        const float inv1 = 1.0f / (reds[(r0 + 8) * 2] + reds[(r0 + 8) * 2 + 1]);

#pragma unroll
        for (int nt = 0; nt < 16; nt++) {
            const int col = wn * 128 + nt * 8 + tig * 2;
            *(uint32_t*)(smc + PH_O + r0 * P_ROW_B + col * 2) =
                pack_h2(acc[nt][0] * inv0, acc[nt][1] * inv0);
            *(uint32_t*)(smc + PH_O + (r0 + 8) * P_ROW_B + col * 2) =
                pack_h2(acc[nt][2] * inv1, acc[nt][3] * inv1);
        }
    }
    __syncthreads();

    const int vrow = tid >> 5;
    const int vc16 = (tid & 31);
    __half* ob = o + qoff;

    uint4 rv0, rv1;
    auto ldgv = [&](int ci) {
        const int s0 = (ci & 15) * 16;
        const int hh = ci >> 4;
        rv0 = *(const uint4*)(Vb + (size_t)(s0 + vrow) * D_ + hh * 256 + vc16 * 8);
        rv1 = *(const uint4*)(Vb + (size_t)(s0 + vrow + 8) * D_ + hh * 256 + vc16 * 8);
    };
    auto stsv = [&](int b) {
        char* base = smc + VH_O + b * V_BUF;
        *(uint4*)(base + vrow * V_ROW_B + vc16 * 16) = rv0;
        *(uint4*)(base + (vrow + 8) * V_ROW_B + vc16 * 16) = rv1;
    };

    for (int h = 0; h < 2; h++) {
        float oacc[16][4];
#pragma unroll
        for (int nt = 0; nt < 16; nt++)
#pragma unroll
            for (int i = 0; i < 4; i++) oacc[nt][i] = 0.0f;

        ldgv(h * 16); stsv(0); ldgv(h * 16 + 1);
        __syncthreads();

        for (int j = 0; j < 16; j++) {
            const int cur = j & 1;
            if (j + 1 < 16) stsv(cur ^ 1);
            if (j + 2 < 16) ldgv(h * 16 + j + 2);

            uint32_t af[4];
            ldsm_x4(af, smb + PH_O + pa + (uint32_t)j * 32);
            const uint32_t vb_ = smb + VH_O + (uint32_t)cur * V_BUF + va;
#pragma unroll
            for (int p = 0; p < 8; p++) {
                uint32_t bf[4];
                ldsm_x4_t(bf, vb_ + (uint32_t)p * 32);
                mma_f16(oacc[2*p    ], af, &bf[0]);
                mma_f16(oacc[2*p + 1], af, &bf[2]);
            }
            __syncthreads();
        }

#pragma unroll
        for (int nt = 0; nt < 16; nt++) {
            const int col = h * 256 + wn * 128 + nt * 8 + tig * 2;
            const int r0  = wm * 16 + g;
            *(uint32_t*)(ob + (size_t)r0 * D_ + col) =
                pack_h2(oacc[nt][0], oacc[nt][1]);
            *(uint32_t*)(ob + (size_t)(r0 + 8) * D_ + col) =
                pack_h2(oacc[nt][2], oacc[nt][3]);
        }
    }
}

// ---------------------------------------------------------------------------
extern "C" void kernel_launch(void* const* d_in, const int* in_sizes, int n_in,
                              void* d_out, int out_size)
{
    (void)in_sizes; (void)n_in; (void)out_size;
    const float* queries = (const float*)d_in[0];
    const float* keys    = (const float*)d_in[1];
    const float* values  = (const float*)d_in[2];
    const float* Wq      = (const float*)d_in[3];
    const float* bq      = (const float*)d_in[4];
    const float* Wkv     = (const float*)d_in[5];
    const float* bkv     = (const float*)d_in[6];
    const float* Wo      = (const float*)d_in[7];
    const float* bo      = (const float*)d_in[8];
    float* out = (float*)d_out;

    __half *qh, *ql, *kh, *kl, *vh, *oh, *whq, *whkv, *who;
    cudaGetSymbolAddress((void**)&qh,   g_qh);
    cudaGetSymbolAddress((void**)&ql,   g_ql);
    cudaGetSymbolAddress((void**)&kh,   g_kh);
    cudaGetSymbolAddress((void**)&kl,   g_kl);
    cudaGetSymbolAddress((void**)&vh,   g_vh);
    cudaGetSymbolAddress((void**)&oh,   g_oh);
    cudaGetSymbolAddress((void**)&whq,  g_whq);
    cudaGetSymbolAddress((void**)&whkv, g_whkv);
    cudaGetSymbolAddress((void**)&who,  g_who);

    (void)cudaFuncSetAttribute(attn_f16_kernel,
                               cudaFuncAttributeMaxDynamicSharedMemorySize,
                               ATTN_SMEM);

    // Weights -> fp16 (one launch)
    convert_w3<<<384, 256>>>(Wq, whq, Wkv, whkv, Wo, who);

    // Fused q/k/v projections
    dim3 gqkv(D_ / 128, NQ / 128, 3);   // (4, 256, 3)
    gemm_qkv<<<gqkv, 256>>>(queries, keys, values, whq, whkv, bq, bkv,
                            qh, ql, kh, kl, vh);

    // Attention
    attn_f16_kernel<<<B_ * L_ * (C_ / 64), 256, ATTN_SMEM>>>(qh, ql, kh, kl, vh, oh);

    // Output projection
    dim3 go(D_ / 128, NQ / 128);        // (4, 256)
    gemm_o<<<go, 256>>>(oh, who, bo, out);
}